// round 6
// baseline (speedup 1.0000x reference)
#include <cuda_runtime.h>
#include <cuda_fp16.h>

#define HDIM   256
#define DK     64
#define NHEADS 4
#define TQ     1024
#define NMAX   24576
#define BTMAX  16384
#define BMAX   64

// ---- scratch (device globals: allocation-free) ----
__device__ float g_Q[TQ * HDIM];
__device__ float g_K[NMAX * HDIM];
__device__ float g_V[NMAX * HDIM];
__device__ float g_ctx[BTMAX * HDIM];
__device__ int   g_starts[BMAX];
__device__ int   g_lens[BMAX];

// ---- packed f32x2 helpers (Blackwell FFMA2 path; ptxas won't auto-fuse) ----
typedef unsigned long long u64;

__device__ __forceinline__ u64 bcast2(float v) {
    u64 r; asm("mov.b64 %0, {%1, %1};" : "=l"(r) : "f"(v)); return r;
}
__device__ __forceinline__ float2 unpack2(u64 v) {
    float2 r; asm("mov.b64 {%0, %1}, %2;" : "=f"(r.x), "=f"(r.y) : "l"(v)); return r;
}
#define FMA2(d, a, b) asm("fma.rn.f32x2 %0, %1, %2, %0;" : "+l"(d) : "l"(a), "l"(b))

// exp2 via MUFU, scalar and packed-half variants
__device__ __forceinline__ float ex2f(float x) {
    float r; asm("ex2.approx.ftz.f32 %0, %1;" : "=f"(r) : "f"(x)); return r;
}
__device__ __forceinline__ float2 ex2_h2(float a, float b) {
    __half2 h = __floats2half2_rn(a, b);
    unsigned hi = *(unsigned*)&h;
    unsigned ho;
    asm("ex2.approx.f16x2 %0, %1;" : "=r"(ho) : "r"(hi));
    return __half22float2(*(__half2*)&ho);
}

// ---- setup: compute segment starts; auto-detect int32 vs int64 lengths ----
__global__ void setup_kernel(const int* __restrict__ lens_raw, int B, int N) {
    if (threadIdx.x != 0 || blockIdx.x != 0) return;
    long long s32 = 0;
    for (int b = 0; b < B; b++) s32 += lens_raw[b];
    int acc = 0;
    if (s32 == (long long)N) {
        for (int b = 0; b < B; b++) { g_starts[b] = acc; g_lens[b] = lens_raw[b]; acc += lens_raw[b]; }
    } else {
        const long long* l64 = (const long long*)lens_raw;
        for (int b = 0; b < B; b++) { int L = (int)l64[b]; g_starts[b] = acc; g_lens[b] = L; acc += L; }
    }
}

// ================= GEMM: Y = X @ W^T, 128x128 tile, split 8x8 microtile =====
__global__ void __launch_bounds__(256, 2) gemm128(
    const float* __restrict__ X, const float* __restrict__ W, float* __restrict__ Y)
{
    __shared__ float Xs[16][132];
    __shared__ float Ws[16][132];

    const int tid = threadIdx.x;
    const int tx = tid & 15, ty = tid >> 4;
    const int m0 = blockIdx.x * 128;
    const int n0 = blockIdx.y * 128;
    const int lr = tid & 127;
    const int lc = (tid >> 7) * 8;

    u64 acc2[8][4];
    #pragma unroll
    for (int r = 0; r < 8; r++)
        #pragma unroll
        for (int p = 0; p < 4; p++) acc2[r][p] = 0ull;

    for (int k0 = 0; k0 < HDIM; k0 += 16) {
        float4 x0 = *(const float4*)&X[(m0 + lr) * HDIM + k0 + lc];
        float4 x1 = *(const float4*)&X[(m0 + lr) * HDIM + k0 + lc + 4];
        float4 w0 = *(const float4*)&W[(n0 + lr) * HDIM + k0 + lc];
        float4 w1 = *(const float4*)&W[(n0 + lr) * HDIM + k0 + lc + 4];
        __syncthreads();
        Xs[lc + 0][lr] = x0.x; Xs[lc + 1][lr] = x0.y; Xs[lc + 2][lr] = x0.z; Xs[lc + 3][lr] = x0.w;
        Xs[lc + 4][lr] = x1.x; Xs[lc + 5][lr] = x1.y; Xs[lc + 6][lr] = x1.z; Xs[lc + 7][lr] = x1.w;
        Ws[lc + 0][lr] = w0.x; Ws[lc + 1][lr] = w0.y; Ws[lc + 2][lr] = w0.z; Ws[lc + 3][lr] = w0.w;
        Ws[lc + 4][lr] = w1.x; Ws[lc + 5][lr] = w1.y; Ws[lc + 6][lr] = w1.z; Ws[lc + 7][lr] = w1.w;
        __syncthreads();

        #pragma unroll
        for (int kk = 0; kk < 16; kk++) {
            float4 a0 = *(const float4*)&Xs[kk][ty * 4];
            float4 a1 = *(const float4*)&Xs[kk][64 + ty * 4];
            ulonglong2 b0 = *(const ulonglong2*)&Ws[kk][tx * 4];
            ulonglong2 b1 = *(const ulonglong2*)&Ws[kk][64 + tx * 4];
            float av[8] = {a0.x, a0.y, a0.z, a0.w, a1.x, a1.y, a1.z, a1.w};
            u64 bb[4] = {b0.x, b0.y, b1.x, b1.y};
            #pragma unroll
            for (int r = 0; r < 8; r++) {
                u64 ar = bcast2(av[r]);
                #pragma unroll
                for (int p = 0; p < 4; p++) FMA2(acc2[r][p], ar, bb[p]);
            }
        }
    }

    #pragma unroll
    for (int i = 0; i < 8; i++) {
        int row = m0 + ((i < 4) ? (ty * 4 + i) : (64 + ty * 4 + i - 4));
        *(ulonglong2*)&Y[row * HDIM + n0 + tx * 4]      = make_ulonglong2(acc2[i][0], acc2[i][1]);
        *(ulonglong2*)&Y[row * HDIM + n0 + 64 + tx * 4] = make_ulonglong2(acc2[i][2], acc2[i][3]);
    }
}

// ================= flash attention over ragged segments =====================
__global__ void __launch_bounds__(256) attn_kernel(int T)
{
    extern __shared__ float sm[];
    float (*Qs)[132] = (float(*)[132])(sm);
    float (*Ks)[132] = (float(*)[132])(sm + 64 * 132);
    float (*Vs)[68]  = (float(*)[68]) (sm + 2 * 64 * 132);
    float (*Ps)[132] = (float(*)[132])(sm + 2 * 64 * 132 + 128 * 68);

    const int t0 = blockIdx.x * 128;
    const int h  = blockIdx.y;
    const int b  = blockIdx.z;
    const int start = g_starts[b];
    const int L     = g_lens[b];

    const int tid = threadIdx.x;
    const int tx = tid & 15, ty = tid >> 4;
    const int lr = tid & 127;
    const int ld = (tid >> 7) * 32;

    #pragma unroll
    for (int p = 0; p < 8; p++) {
        float4 q = *(const float4*)&g_Q[(t0 + lr) * HDIM + h * DK + ld + p * 4];
        Qs[ld + p * 4 + 0][lr] = q.x; Qs[ld + p * 4 + 1][lr] = q.y;
        Qs[ld + p * 4 + 2][lr] = q.z; Qs[ld + p * 4 + 3][lr] = q.w;
    }

    u64 o2[8][2];
    float m[8], l[8];
    #pragma unroll
    for (int i = 0; i < 8; i++) {
        m[i] = -1e30f; l[i] = 0.f;
        o2[i][0] = 0ull; o2[i][1] = 0ull;
    }

    // log2-domain scale: 1/(sqrt(DK)*TEMP) * log2(e)
    const float sc = 0.125f * 1.4426950408889634f;

    for (int l0 = 0; l0 < L; l0 += 128) {
        __syncthreads();
        {
            int li = l0 + lr; if (li > L - 1) li = L - 1;
            int node = start + li;
            #pragma unroll
            for (int p = 0; p < 8; p++) {
                float4 kv = *(const float4*)&g_K[node * HDIM + h * DK + ld + p * 4];
                Ks[ld + p * 4 + 0][lr] = kv.x; Ks[ld + p * 4 + 1][lr] = kv.y;
                Ks[ld + p * 4 + 2][lr] = kv.z; Ks[ld + p * 4 + 3][lr] = kv.w;
                float4 vv = *(const float4*)&g_V[node * HDIM + h * DK + ld + p * 4];
                *(float4*)&Vs[lr][ld + p * 4] = vv;
            }
        }
        __syncthreads();

        // S = Q @ K^T, packed f32x2
        u64 s2[8][4];
        #pragma unroll
        for (int r = 0; r < 8; r++)
            #pragma unroll
            for (int p = 0; p < 4; p++) s2[r][p] = 0ull;

        #pragma unroll 8
        for (int d = 0; d < 64; d++) {
            float4 a0 = *(const float4*)&Qs[d][ty * 4];
            float4 a1 = *(const float4*)&Qs[d][64 + ty * 4];
            ulonglong2 b0 = *(const ulonglong2*)&Ks[d][tx * 4];
            ulonglong2 b1 = *(const ulonglong2*)&Ks[d][64 + tx * 4];
            float av[8] = {a0.x, a0.y, a0.z, a0.w, a1.x, a1.y, a1.z, a1.w};
            u64 bb[4] = {b0.x, b0.y, b1.x, b1.y};
            #pragma unroll
            for (int r = 0; r < 8; r++) {
                u64 ar = bcast2(av[r]);
                #pragma unroll
                for (int p = 0; p < 4; p++) FMA2(s2[r][p], ar, bb[p]);
            }
        }

        // unpack, scale (log2 domain) + ragged tail mask
        float s[8][8];
        #pragma unroll
        for (int r = 0; r < 8; r++)
            #pragma unroll
            for (int p = 0; p < 4; p++) {
                float2 u = unpack2(s2[r][p]);
                s[r][p * 2] = u.x; s[r][p * 2 + 1] = u.y;
            }

        const bool tail = (l0 + 128 > L);
        #pragma unroll
        for (int i = 0; i < 8; i++)
            #pragma unroll
            for (int j = 0; j < 8; j++) {
                float v = s[i][j] * sc;
                if (tail) {
                    int col = l0 + ((j < 4) ? (tx * 4 + j) : (64 + tx * 4 + j - 4));
                    if (col >= L) v = -1e30f;
                }
                s[i][j] = v;
            }

        // online softmax per row; exps via packed f16x2 MUFU (2 exps / MUFU op)
        float sf[8];
        #pragma unroll
        for (int i = 0; i < 8; i++) {
            float mx = s[i][0];
            #pragma unroll
            for (int j = 1; j < 8; j++) mx = fmaxf(mx, s[i][j]);
            #pragma unroll
            for (int off = 8; off; off >>= 1)
                mx = fmaxf(mx, __shfl_xor_sync(0xffffffffu, mx, off));
            float mn = fmaxf(m[i], mx);
            sf[i] = ex2f(m[i] - mn);
            float rs = 0.f;
            #pragma unroll
            for (int p = 0; p < 4; p++) {
                float2 e = ex2_h2(s[i][2 * p] - mn, s[i][2 * p + 1] - mn);
                s[i][2 * p] = e.x; s[i][2 * p + 1] = e.y;
                rs += e.x + e.y;
            }
            #pragma unroll
            for (int off = 8; off; off >>= 1)
                rs += __shfl_xor_sync(0xffffffffu, rs, off);
            m[i] = mn;
            l[i] = l[i] * sf[i] + rs;
        }
        // rescale packed O accumulators
        #pragma unroll
        for (int i = 0; i < 8; i++) {
            u64 fi = bcast2(sf[i]);
            u64 z0 = 0ull, z1 = 0ull;
            FMA2(z0, o2[i][0], fi); FMA2(z1, o2[i][1], fi);
            o2[i][0] = z0; o2[i][1] = z1;
        }

        // store P transposed with XOR swizzle
        #pragma unroll
        for (int j = 0; j < 8; j++) {
            int c = (j < 4) ? (tx * 4 + j) : (64 + tx * 4 + j - 4);
            int f = ((c >> 3) & 3) << 2;
            int r0 = (ty * 4) ^ f;
            *(float4*)&Ps[c][r0]      = make_float4(s[0][j], s[1][j], s[2][j], s[3][j]);
            *(float4*)&Ps[c][64 + r0] = make_float4(s[4][j], s[5][j], s[6][j], s[7][j]);
        }
        __syncthreads();

        // O += P @ V, packed f32x2
        #pragma unroll 4
        for (int kl = 0; kl < 128; kl++) {
            int sr = (ty * 4) ^ (((kl >> 3) & 3) << 2);
            float4 a0 = *(const float4*)&Ps[kl][sr];
            float4 a1 = *(const float4*)&Ps[kl][64 + sr];
            ulonglong2 bv = *(const ulonglong2*)&Vs[kl][tx * 4];
            float av[8] = {a0.x, a0.y, a0.z, a0.w, a1.x, a1.y, a1.z, a1.w};
            #pragma unroll
            for (int r = 0; r < 8; r++) {
                u64 ar = bcast2(av[r]);
                FMA2(o2[r][0], ar, bv.x);
                FMA2(o2[r][1], ar, bv.y);
            }
        }
    }

    // epilogue: normalize, write ctx
    #pragma unroll
    for (int i = 0; i < 8; i++) {
        int r = (i < 4) ? (ty * 4 + i) : (64 + ty * 4 + i - 4);
        float inv = 1.f / l[i];
        float2 p0 = unpack2(o2[i][0]);
        float2 p1 = unpack2(o2[i][1]);
        int row = b * T + t0 + r;
        *(float4*)&g_ctx[row * HDIM + h * DK + tx * 4] =
            make_float4(p0.x * inv, p0.y * inv, p1.x * inv, p1.y * inv);
    }
}

extern "C" void kernel_launch(void* const* d_in, const int* in_sizes, int n_in,
                              void* d_out, int out_size)
{
    const float* go   = (const float*)d_in[0];
    const float* node = (const float*)d_in[1];
    const float* Wq   = (const float*)d_in[2];
    const float* Wk   = (const float*)d_in[3];
    const float* Wv   = (const float*)d_in[4];
    const float* Wp   = (const float*)d_in[5];
    const int*   lens = (const int*)d_in[6];
    float* out = (float*)d_out;

    const int T = in_sizes[0] / HDIM;   // 1024
    const int N = in_sizes[1] / HDIM;   // 24576
    const int B = in_sizes[6];          // 16

    float *pQ, *pK, *pV, *pC;
    cudaGetSymbolAddress((void**)&pQ, g_Q);
    cudaGetSymbolAddress((void**)&pK, g_K);
    cudaGetSymbolAddress((void**)&pV, g_V);
    cudaGetSymbolAddress((void**)&pC, g_ctx);

    setup_kernel<<<1, 32>>>(lens, B, N);

    dim3 blk(256);
    gemm128<<<dim3(T / 128, 2), blk>>>(go, Wq, pQ);
    gemm128<<<dim3(N / 128, 2), blk>>>(node, Wk, pK);
    gemm128<<<dim3(N / 128, 2), blk>>>(node, Wv, pV);

    int smem = (2 * 64 * 132 + 128 * 68 + 128 * 132) * (int)sizeof(float);   // 169984 B
    cudaFuncSetAttribute(attn_kernel, cudaFuncAttributeMaxDynamicSharedMemorySize, smem);
    attn_kernel<<<dim3(T / 128, NHEADS, B), blk, smem>>>(T);

    gemm128<<<dim3((B * T) / 128, 2), blk>>>(pC, Wp, out);
}

// round 7
// speedup vs baseline: 1.6750x; 1.6750x over previous
#include <cuda_runtime.h>
#include <cuda_fp16.h>

#define HDIM   256
#define DK     64
#define NHEADS 4
#define TQ     1024
#define NMAX   24576
#define BTMAX  16384
#define BMAX   64

// ---- scratch (device globals: allocation-free) ----
__device__ float g_Q[TQ * HDIM];
__device__ float g_K[NMAX * HDIM];
__device__ float g_V[NMAX * HDIM];
__device__ float g_ctx[BTMAX * HDIM];
__device__ int   g_starts[BMAX];
__device__ int   g_lens[BMAX];

// ---- packed f32x2 helpers (Blackwell FFMA2 path; ptxas won't auto-fuse) ----
typedef unsigned long long u64;

__device__ __forceinline__ u64 bcast2(float v) {
    u64 r; asm("mov.b64 %0, {%1, %1};" : "=l"(r) : "f"(v)); return r;
}
__device__ __forceinline__ float2 unpack2(u64 v) {
    float2 r; asm("mov.b64 {%0, %1}, %2;" : "=f"(r.x), "=f"(r.y) : "l"(v)); return r;
}
#define FMA2(d, a, b) asm("fma.rn.f32x2 %0, %1, %2, %0;" : "+l"(d) : "l"(a), "l"(b))

// exp2 via MUFU, scalar and packed-half variants
__device__ __forceinline__ float ex2f(float x) {
    float r; asm("ex2.approx.ftz.f32 %0, %1;" : "=f"(r) : "f"(x)); return r;
}
__device__ __forceinline__ float2 ex2_h2(float a, float b) {
    __half2 h = __floats2half2_rn(a, b);
    unsigned hi = *(unsigned*)&h;
    unsigned ho;
    asm("ex2.approx.f16x2 %0, %1;" : "=r"(ho) : "r"(hi));
    return __half22float2(*(__half2*)&ho);
}

// ---- setup: compute segment starts; auto-detect int32 vs int64 lengths ----
__global__ void setup_kernel(const int* __restrict__ lens_raw, int B, int N) {
    if (threadIdx.x != 0 || blockIdx.x != 0) return;
    long long s32 = 0;
    for (int b = 0; b < B; b++) s32 += lens_raw[b];
    int acc = 0;
    if (s32 == (long long)N) {
        for (int b = 0; b < B; b++) { g_starts[b] = acc; g_lens[b] = lens_raw[b]; acc += lens_raw[b]; }
    } else {
        const long long* l64 = (const long long*)lens_raw;
        for (int b = 0; b < B; b++) { int L = (int)l64[b]; g_starts[b] = acc; g_lens[b] = L; acc += L; }
    }
}

// ================= GEMM: Y = X @ W^T, 128x128 tile, split 8x8 microtile =====
// Register-prefetch double buffering: next k-tile's global loads are issued
// before the current tile's FFMA2 block, hiding L2 latency behind compute.
__global__ void __launch_bounds__(256, 2) gemm128(
    const float* __restrict__ X, const float* __restrict__ W, float* __restrict__ Y)
{
    __shared__ float Xs[16][132];
    __shared__ float Ws[16][132];

    const int tid = threadIdx.x;
    const int tx = tid & 15, ty = tid >> 4;
    const int m0 = blockIdx.x * 128;
    const int n0 = blockIdx.y * 128;
    const int lr = tid & 127;
    const int lc = (tid >> 7) * 8;

    const float* xp = &X[(m0 + lr) * HDIM + lc];
    const float* wp = &W[(n0 + lr) * HDIM + lc];

    u64 acc2[8][4];
    #pragma unroll
    for (int r = 0; r < 8; r++)
        #pragma unroll
        for (int p = 0; p < 4; p++) acc2[r][p] = 0ull;

    // prologue: load first k-tile into regs
    float4 x0 = *(const float4*)(xp);
    float4 x1 = *(const float4*)(xp + 4);
    float4 w0 = *(const float4*)(wp);
    float4 w1 = *(const float4*)(wp + 4);

    #pragma unroll
    for (int k0 = 0; k0 < HDIM; k0 += 16) {
        __syncthreads();   // prior compute finished reading smem
        Xs[lc + 0][lr] = x0.x; Xs[lc + 1][lr] = x0.y; Xs[lc + 2][lr] = x0.z; Xs[lc + 3][lr] = x0.w;
        Xs[lc + 4][lr] = x1.x; Xs[lc + 5][lr] = x1.y; Xs[lc + 6][lr] = x1.z; Xs[lc + 7][lr] = x1.w;
        Ws[lc + 0][lr] = w0.x; Ws[lc + 1][lr] = w0.y; Ws[lc + 2][lr] = w0.z; Ws[lc + 3][lr] = w0.w;
        Ws[lc + 4][lr] = w1.x; Ws[lc + 5][lr] = w1.y; Ws[lc + 6][lr] = w1.z; Ws[lc + 7][lr] = w1.w;
        __syncthreads();

        if (k0 + 16 < HDIM) {   // prefetch next tile (overlaps with compute below)
            x0 = *(const float4*)(xp + k0 + 16);
            x1 = *(const float4*)(xp + k0 + 20);
            w0 = *(const float4*)(wp + k0 + 16);
            w1 = *(const float4*)(wp + k0 + 20);
        }

        #pragma unroll
        for (int kk = 0; kk < 16; kk++) {
            float4 a0 = *(const float4*)&Xs[kk][ty * 4];
            float4 a1 = *(const float4*)&Xs[kk][64 + ty * 4];
            ulonglong2 b0 = *(const ulonglong2*)&Ws[kk][tx * 4];
            ulonglong2 b1 = *(const ulonglong2*)&Ws[kk][64 + tx * 4];
            float av[8] = {a0.x, a0.y, a0.z, a0.w, a1.x, a1.y, a1.z, a1.w};
            u64 bb[4] = {b0.x, b0.y, b1.x, b1.y};
            #pragma unroll
            for (int r = 0; r < 8; r++) {
                u64 ar = bcast2(av[r]);
                #pragma unroll
                for (int p = 0; p < 4; p++) FMA2(acc2[r][p], ar, bb[p]);
            }
        }
    }

    #pragma unroll
    for (int i = 0; i < 8; i++) {
        int row = m0 + ((i < 4) ? (ty * 4 + i) : (64 + ty * 4 + i - 4));
        *(ulonglong2*)&Y[row * HDIM + n0 + tx * 4]      = make_ulonglong2(acc2[i][0], acc2[i][1]);
        *(ulonglong2*)&Y[row * HDIM + n0 + 64 + tx * 4] = make_ulonglong2(acc2[i][2], acc2[i][3]);
    }
}

// ================= flash attention over ragged segments =====================
__global__ void __launch_bounds__(256) attn_kernel(int T)
{
    extern __shared__ float sm[];
    float (*Qs)[132] = (float(*)[132])(sm);
    float (*Ks)[132] = (float(*)[132])(sm + 64 * 132);
    float (*Vs)[68]  = (float(*)[68]) (sm + 2 * 64 * 132);
    float (*Ps)[132] = (float(*)[132])(sm + 2 * 64 * 132 + 128 * 68);

    const int t0 = blockIdx.x * 128;
    const int h  = blockIdx.y;
    const int b  = blockIdx.z;
    const int start = g_starts[b];
    const int L     = g_lens[b];

    const int tid = threadIdx.x;
    const int tx = tid & 15, ty = tid >> 4;
    const int lr = tid & 127;
    const int ld = (tid >> 7) * 32;

    #pragma unroll
    for (int p = 0; p < 8; p++) {
        float4 q = *(const float4*)&g_Q[(t0 + lr) * HDIM + h * DK + ld + p * 4];
        Qs[ld + p * 4 + 0][lr] = q.x; Qs[ld + p * 4 + 1][lr] = q.y;
        Qs[ld + p * 4 + 2][lr] = q.z; Qs[ld + p * 4 + 3][lr] = q.w;
    }

    u64 o2[8][2];
    float m[8], l[8];
    #pragma unroll
    for (int i = 0; i < 8; i++) {
        m[i] = -1e30f; l[i] = 0.f;
        o2[i][0] = 0ull; o2[i][1] = 0ull;
    }

    // log2-domain scale: 1/(sqrt(DK)*TEMP) * log2(e)
    const float sc = 0.125f * 1.4426950408889634f;

    for (int l0 = 0; l0 < L; l0 += 128) {
        __syncthreads();
        {
            int li = l0 + lr; if (li > L - 1) li = L - 1;
            int node = start + li;
            #pragma unroll
            for (int p = 0; p < 8; p++) {
                float4 kv = *(const float4*)&g_K[node * HDIM + h * DK + ld + p * 4];
                Ks[ld + p * 4 + 0][lr] = kv.x; Ks[ld + p * 4 + 1][lr] = kv.y;
                Ks[ld + p * 4 + 2][lr] = kv.z; Ks[ld + p * 4 + 3][lr] = kv.w;
                float4 vv = *(const float4*)&g_V[node * HDIM + h * DK + ld + p * 4];
                *(float4*)&Vs[lr][ld + p * 4] = vv;
            }
        }
        __syncthreads();

        // S = Q @ K^T, packed f32x2
        u64 s2[8][4];
        #pragma unroll
        for (int r = 0; r < 8; r++)
            #pragma unroll
            for (int p = 0; p < 4; p++) s2[r][p] = 0ull;

        #pragma unroll 8
        for (int d = 0; d < 64; d++) {
            float4 a0 = *(const float4*)&Qs[d][ty * 4];
            float4 a1 = *(const float4*)&Qs[d][64 + ty * 4];
            ulonglong2 b0 = *(const ulonglong2*)&Ks[d][tx * 4];
            ulonglong2 b1 = *(const ulonglong2*)&Ks[d][64 + tx * 4];
            float av[8] = {a0.x, a0.y, a0.z, a0.w, a1.x, a1.y, a1.z, a1.w};
            u64 bb[4] = {b0.x, b0.y, b1.x, b1.y};
            #pragma unroll
            for (int r = 0; r < 8; r++) {
                u64 ar = bcast2(av[r]);
                #pragma unroll
                for (int p = 0; p < 4; p++) FMA2(s2[r][p], ar, bb[p]);
            }
        }

        // unpack, scale (log2 domain) + ragged tail mask
        float s[8][8];
        #pragma unroll
        for (int r = 0; r < 8; r++)
            #pragma unroll
            for (int p = 0; p < 4; p++) {
                float2 u = unpack2(s2[r][p]);
                s[r][p * 2] = u.x; s[r][p * 2 + 1] = u.y;
            }

        const bool tail = (l0 + 128 > L);
        #pragma unroll
        for (int i = 0; i < 8; i++)
            #pragma unroll
            for (int j = 0; j < 8; j++) {
                float v = s[i][j] * sc;
                if (tail) {
                    int col = l0 + ((j < 4) ? (tx * 4 + j) : (64 + tx * 4 + j - 4));
                    if (col >= L) v = -1e30f;
                }
                s[i][j] = v;
            }

        // online softmax per row; exps via packed f16x2 MUFU (2 exps / MUFU op)
        float sf[8];
        #pragma unroll
        for (int i = 0; i < 8; i++) {
            float mx = s[i][0];
            #pragma unroll
            for (int j = 1; j < 8; j++) mx = fmaxf(mx, s[i][j]);
            #pragma unroll
            for (int off = 8; off; off >>= 1)
                mx = fmaxf(mx, __shfl_xor_sync(0xffffffffu, mx, off));
            float mn = fmaxf(m[i], mx);
            sf[i] = ex2f(m[i] - mn);
            float rs = 0.f;
            #pragma unroll
            for (int p = 0; p < 4; p++) {
                float2 e = ex2_h2(s[i][2 * p] - mn, s[i][2 * p + 1] - mn);
                s[i][2 * p] = e.x; s[i][2 * p + 1] = e.y;
                rs += e.x + e.y;
            }
            #pragma unroll
            for (int off = 8; off; off >>= 1)
                rs += __shfl_xor_sync(0xffffffffu, rs, off);
            m[i] = mn;
            l[i] = l[i] * sf[i] + rs;
        }
        // rescale packed O accumulators
        #pragma unroll
        for (int i = 0; i < 8; i++) {
            u64 fi = bcast2(sf[i]);
            u64 z0 = 0ull, z1 = 0ull;
            FMA2(z0, o2[i][0], fi); FMA2(z1, o2[i][1], fi);
            o2[i][0] = z0; o2[i][1] = z1;
        }

        // store P transposed with XOR swizzle
        #pragma unroll
        for (int j = 0; j < 8; j++) {
            int c = (j < 4) ? (tx * 4 + j) : (64 + tx * 4 + j - 4);
            int f = ((c >> 3) & 3) << 2;
            int r0 = (ty * 4) ^ f;
            *(float4*)&Ps[c][r0]      = make_float4(s[0][j], s[1][j], s[2][j], s[3][j]);
            *(float4*)&Ps[c][64 + r0] = make_float4(s[4][j], s[5][j], s[6][j], s[7][j]);
        }
        __syncthreads();

        // O += P @ V, packed f32x2
        #pragma unroll 4
        for (int kl = 0; kl < 128; kl++) {
            int sr = (ty * 4) ^ (((kl >> 3) & 3) << 2);
            float4 a0 = *(const float4*)&Ps[kl][sr];
            float4 a1 = *(const float4*)&Ps[kl][64 + sr];
            ulonglong2 bv = *(const ulonglong2*)&Vs[kl][tx * 4];
            float av[8] = {a0.x, a0.y, a0.z, a0.w, a1.x, a1.y, a1.z, a1.w};
            #pragma unroll
            for (int r = 0; r < 8; r++) {
                u64 ar = bcast2(av[r]);
                FMA2(o2[r][0], ar, bv.x);
                FMA2(o2[r][1], ar, bv.y);
            }
        }
    }

    // epilogue: normalize, write ctx
    #pragma unroll
    for (int i = 0; i < 8; i++) {
        int r = (i < 4) ? (ty * 4 + i) : (64 + ty * 4 + i - 4);
        float inv = 1.f / l[i];
        float2 p0 = unpack2(o2[i][0]);
        float2 p1 = unpack2(o2[i][1]);
        int row = b * T + t0 + r;
        *(float4*)&g_ctx[row * HDIM + h * DK + tx * 4] =
            make_float4(p0.x * inv, p0.y * inv, p1.x * inv, p1.y * inv);
    }
}

extern "C" void kernel_launch(void* const* d_in, const int* in_sizes, int n_in,
                              void* d_out, int out_size)
{
    const float* go   = (const float*)d_in[0];
    const float* node = (const float*)d_in[1];
    const float* Wq   = (const float*)d_in[2];
    const float* Wk   = (const float*)d_in[3];
    const float* Wv   = (const float*)d_in[4];
    const float* Wp   = (const float*)d_in[5];
    const int*   lens = (const int*)d_in[6];
    float* out = (float*)d_out;

    const int T = in_sizes[0] / HDIM;   // 1024
    const int N = in_sizes[1] / HDIM;   // 24576
    const int B = in_sizes[6];          // 16

    float *pQ, *pK, *pV, *pC;
    cudaGetSymbolAddress((void**)&pQ, g_Q);
    cudaGetSymbolAddress((void**)&pK, g_K);
    cudaGetSymbolAddress((void**)&pV, g_V);
    cudaGetSymbolAddress((void**)&pC, g_ctx);

    setup_kernel<<<1, 32>>>(lens, B, N);

    dim3 blk(256);
    gemm128<<<dim3(T / 128, 2), blk>>>(go, Wq, pQ);
    gemm128<<<dim3(N / 128, 2), blk>>>(node, Wk, pK);
    gemm128<<<dim3(N / 128, 2), blk>>>(node, Wv, pV);

    int smem = (2 * 64 * 132 + 128 * 68 + 128 * 132) * (int)sizeof(float);   // 169984 B
    cudaFuncSetAttribute(attn_kernel, cudaFuncAttributeMaxDynamicSharedMemorySize, smem);
    attn_kernel<<<dim3(T / 128, NHEADS, B), blk, smem>>>(T);

    gemm128<<<dim3((B * T) / 128, 2), blk>>>(pC, Wp, out);
}

// round 11
// speedup vs baseline: 3.9786x; 2.3753x over previous
#include <cuda_runtime.h>
#include <cuda_fp16.h>
#include <cstdint>

#define HDIM   256
#define DK     64
#define NHEADS 4
#define TQ     1024
#define NMAX   24576
#define BTMAX  16384
#define BMAX   64

// ---- scratch (device globals: allocation-free) ----
__device__ __half g_Qh[TQ * HDIM];
__device__ __half g_Kh[NMAX * HDIM];
__device__ __half g_Vh[NMAX * HDIM];
__device__ float  g_ctx[BTMAX * HDIM];
__device__ int    g_starts[BMAX];
__device__ int    g_lens[BMAX];

typedef unsigned long long u64;

// ---- packed f32x2 helpers ----
__device__ __forceinline__ u64 bcast2(float v) {
    u64 r; asm("mov.b64 %0, {%1, %1};" : "=l"(r) : "f"(v)); return r;
}
__device__ __forceinline__ float2 unpack2(u64 v) {
    float2 r; asm("mov.b64 {%0, %1}, %2;" : "=f"(r.x), "=f"(r.y) : "l"(v)); return r;
}
#define FMA2(d, a, b) asm("fma.rn.f32x2 %0, %1, %2, %0;" : "+l"(d) : "l"(a), "l"(b))

__device__ __forceinline__ float ex2f(float x) {
    float r; asm("ex2.approx.ftz.f32 %0, %1;" : "=f"(r) : "f"(x)); return r;
}
// packed-half exp2: returns raw f16x2 bits AND f32 values
__device__ __forceinline__ uint32_t ex2_h2raw(float a, float b, float2* out) {
    __half2 h = __floats2half2_rn(a, b);
    uint32_t hi = *(uint32_t*)&h, ho;
    asm("ex2.approx.f16x2 %0, %1;" : "=r"(ho) : "r"(hi));
    __half2 r = *(__half2*)&ho;
    *out = __half22float2(r);
    return ho;
}
__device__ __forceinline__ uint32_t f2h2(u64 v) {
    float2 f = unpack2(v);
    __half2 h = __floats2half2_rn(f.x, f.y);
    return *(uint32_t*)&h;
}

__device__ __forceinline__ uint32_t smem_u32(const void* p) {
    uint32_t a;
    asm("{ .reg .u64 t; cvta.to.shared.u64 t, %1; cvt.u32.u64 %0, t; }" : "=r"(a) : "l"(p));
    return a;
}

// ---- mma.sync + ldmatrix wrappers (sm_80+, no 'a' target needed) ----
__device__ __forceinline__ void ldsm_x4(uint32_t& r0, uint32_t& r1, uint32_t& r2, uint32_t& r3, uint32_t a) {
    asm volatile("ldmatrix.sync.aligned.m8n8.x4.shared.b16 {%0,%1,%2,%3}, [%4];"
                 : "=r"(r0), "=r"(r1), "=r"(r2), "=r"(r3) : "r"(a));
}
__device__ __forceinline__ void ldsm_x4_t(uint32_t& r0, uint32_t& r1, uint32_t& r2, uint32_t& r3, uint32_t a) {
    asm volatile("ldmatrix.sync.aligned.m8n8.x4.trans.shared.b16 {%0,%1,%2,%3}, [%4];"
                 : "=r"(r0), "=r"(r1), "=r"(r2), "=r"(r3) : "r"(a));
}
__device__ __forceinline__ void mma16816(float* c, const uint32_t* a, uint32_t b0, uint32_t b1) {
    asm volatile("mma.sync.aligned.m16n8k16.row.col.f32.f16.f16.f32 "
                 "{%0,%1,%2,%3}, {%4,%5,%6,%7}, {%8,%9}, {%0,%1,%2,%3};"
                 : "+f"(c[0]), "+f"(c[1]), "+f"(c[2]), "+f"(c[3])
                 : "r"(a[0]), "r"(a[1]), "r"(a[2]), "r"(a[3]), "r"(b0), "r"(b1));
}

// byte OFFSET within a [row][64 halves] tile (128B rows, XOR-16B swizzle)
__device__ __forceinline__ uint32_t sw_off(int row, int dhalf) {
    int c = (dhalf >> 3) ^ (row & 7);
    return (uint32_t)(row * 128 + c * 16 + (dhalf & 7) * 2);
}

// ---- setup: compute segment starts; auto-detect int32 vs int64 lengths ----
__global__ void setup_kernel(const int* __restrict__ lens_raw, int B, int N) {
    if (threadIdx.x != 0 || blockIdx.x != 0) return;
    long long s32 = 0;
    for (int b = 0; b < B; b++) s32 += lens_raw[b];
    int acc = 0;
    if (s32 == (long long)N) {
        for (int b = 0; b < B; b++) { g_starts[b] = acc; g_lens[b] = lens_raw[b]; acc += lens_raw[b]; }
    } else {
        const long long* l64 = (const long long*)lens_raw;
        for (int b = 0; b < B; b++) { int L = (int)l64[b]; g_starts[b] = acc; g_lens[b] = L; acc += L; }
    }
}

// ================= GEMM: Y = X @ W^T (f32 compute; f32 or f16 output) =======
template <bool HOUT>
__global__ void __launch_bounds__(256, 2) gemm128(
    const float* __restrict__ X, const float* __restrict__ W,
    float* __restrict__ Y, __half* __restrict__ Yh)
{
    __shared__ float Xs[16][132];
    __shared__ float Ws[16][132];

    const int tid = threadIdx.x;
    const int tx = tid & 15, ty = tid >> 4;
    const int m0 = blockIdx.x * 128;
    const int n0 = blockIdx.y * 128;
    const int lr = tid & 127;
    const int lc = (tid >> 7) * 8;

    const float* xp = &X[(m0 + lr) * HDIM + lc];
    const float* wp = &W[(n0 + lr) * HDIM + lc];

    u64 acc2[8][4];
    #pragma unroll
    for (int r = 0; r < 8; r++)
        #pragma unroll
        for (int p = 0; p < 4; p++) acc2[r][p] = 0ull;

    float4 x0 = *(const float4*)(xp);
    float4 x1 = *(const float4*)(xp + 4);
    float4 w0 = *(const float4*)(wp);
    float4 w1 = *(const float4*)(wp + 4);

    #pragma unroll
    for (int k0 = 0; k0 < HDIM; k0 += 16) {
        __syncthreads();
        Xs[lc + 0][lr] = x0.x; Xs[lc + 1][lr] = x0.y; Xs[lc + 2][lr] = x0.z; Xs[lc + 3][lr] = x0.w;
        Xs[lc + 4][lr] = x1.x; Xs[lc + 5][lr] = x1.y; Xs[lc + 6][lr] = x1.z; Xs[lc + 7][lr] = x1.w;
        Ws[lc + 0][lr] = w0.x; Ws[lc + 1][lr] = w0.y; Ws[lc + 2][lr] = w0.z; Ws[lc + 3][lr] = w0.w;
        Ws[lc + 4][lr] = w1.x; Ws[lc + 5][lr] = w1.y; Ws[lc + 6][lr] = w1.z; Ws[lc + 7][lr] = w1.w;
        __syncthreads();

        if (k0 + 16 < HDIM) {
            x0 = *(const float4*)(xp + k0 + 16);
            x1 = *(const float4*)(xp + k0 + 20);
            w0 = *(const float4*)(wp + k0 + 16);
            w1 = *(const float4*)(wp + k0 + 20);
        }

        #pragma unroll
        for (int kk = 0; kk < 16; kk++) {
            float4 a0 = *(const float4*)&Xs[kk][ty * 4];
            float4 a1 = *(const float4*)&Xs[kk][64 + ty * 4];
            ulonglong2 b0 = *(const ulonglong2*)&Ws[kk][tx * 4];
            ulonglong2 b1 = *(const ulonglong2*)&Ws[kk][64 + tx * 4];
            float av[8] = {a0.x, a0.y, a0.z, a0.w, a1.x, a1.y, a1.z, a1.w};
            u64 bb[4] = {b0.x, b0.y, b1.x, b1.y};
            #pragma unroll
            for (int r = 0; r < 8; r++) {
                u64 ar = bcast2(av[r]);
                #pragma unroll
                for (int p = 0; p < 4; p++) FMA2(acc2[r][p], ar, bb[p]);
            }
        }
    }

    #pragma unroll
    for (int i = 0; i < 8; i++) {
        int row = m0 + ((i < 4) ? (ty * 4 + i) : (64 + ty * 4 + i - 4));
        if (HOUT) {
            uint2 v0 = make_uint2(f2h2(acc2[i][0]), f2h2(acc2[i][1]));
            uint2 v1 = make_uint2(f2h2(acc2[i][2]), f2h2(acc2[i][3]));
            *(uint2*)&Yh[row * HDIM + n0 + tx * 4]      = v0;
            *(uint2*)&Yh[row * HDIM + n0 + 64 + tx * 4] = v1;
        } else {
            *(ulonglong2*)&Y[row * HDIM + n0 + tx * 4]      = make_ulonglong2(acc2[i][0], acc2[i][1]);
            *(ulonglong2*)&Y[row * HDIM + n0 + 64 + tx * 4] = make_ulonglong2(acc2[i][2], acc2[i][3]);
        }
    }
}

// ================= HMMA flash attention over ragged segments ================
// grid (T/128, NHEADS, B), 256 threads = 8 warps; warp owns 16 q-rows.
// Chunks of 128 keys. Q/K/V in swizzled smem; P stays in registers (C->A reuse).
__global__ void __launch_bounds__(256) attn_mma(int T)
{
    __shared__ __half Qs[128 * 64];
    __shared__ __half Ks[128 * 64];
    __shared__ __half Vs[128 * 64];

    const uint32_t qb_s = smem_u32(Qs);
    const uint32_t kb_s = smem_u32(Ks);
    const uint32_t vb_s = smem_u32(Vs);

    const int tid = threadIdx.x, wid = tid >> 5, ln = tid & 31;
    const int t0 = blockIdx.x * 128, h = blockIdx.y, b = blockIdx.z;
    const int start = g_starts[b], L = g_lens[b];
    const int qb = wid * 16;                    // warp's q-row base within tile

    // stage Q tile: row = tid>>1, seg = tid&1 covers dhalf seg*32 .. +31
    // uint4 = 16 B = 8 halves per step, matching the 8-half offset stride.
    {
        int row = tid >> 1, seg = tid & 1;
        const uint4* src = (const uint4*)(g_Qh + (size_t)(t0 + row) * HDIM + h * DK + seg * 32);
        #pragma unroll
        for (int j = 0; j < 4; j++) {
            uint4 v = src[j];
            *(uint4*)((char*)Qs + sw_off(row, seg * 32 + j * 8)) = v;
        }
    }
    __syncthreads();

    // Q A-fragments: constant across all chunks — load once
    uint32_t qa[4][4];
    #pragma unroll
    for (int t = 0; t < 4; t++) {
        uint32_t addr = qb_s + sw_off(qb + (ln & 15), t * 16 + (ln >> 4) * 8);
        ldsm_x4(qa[t][0], qa[t][1], qa[t][2], qa[t][3], addr);
    }

    float oacc[8][4];
    #pragma unroll
    for (int i = 0; i < 8; i++)
        #pragma unroll
        for (int q = 0; q < 4; q++) oacc[i][q] = 0.f;
    float mrun[2] = {-1e30f, -1e30f};
    float lrun[2] = {0.f, 0.f};

    const float sc = 0.125f * 1.4426950408889634f;   // 1/sqrt(DK)/TEMP * log2(e)

    for (int l0 = 0; l0 < L; l0 += 128) {
        __syncthreads();   // all warps done reading K/V smem from prior chunk
        // stage K and V chunk
        {
            int row = tid >> 1, seg = tid & 1;
            int li = l0 + row; if (li > L - 1) li = L - 1;
            size_t node = (size_t)(start + li);
            const uint4* ksrc = (const uint4*)(g_Kh + node * HDIM + h * DK + seg * 32);
            const uint4* vsrc = (const uint4*)(g_Vh + node * HDIM + h * DK + seg * 32);
            #pragma unroll
            for (int j = 0; j < 4; j++) {
                uint4 kv = ksrc[j];
                uint4 vv = vsrc[j];
                uint32_t off = sw_off(row, seg * 32 + j * 8);
                *(uint4*)((char*)Ks + off) = kv;
                *(uint4*)((char*)Vs + off) = vv;
            }
        }
        __syncthreads();

        // ---- S = Q @ K^T : 16 n8-tiles (tile i covers keys 8i..8i+7) ----
        float sacc[16][4];
        #pragma unroll
        for (int i = 0; i < 16; i++)
            #pragma unroll
            for (int q = 0; q < 4; q++) sacc[i][q] = 0.f;

        #pragma unroll
        for (int t = 0; t < 4; t++) {          // k16 over d
            #pragma unroll
            for (int j = 0; j < 8; j++) {      // n16 over keys
                uint32_t b0, b1, b2, b3;
                uint32_t addr = kb_s + sw_off(
                    j * 16 + ((ln >> 4) & 1) * 8 + (ln & 7),
                    t * 16 + ((ln >> 3) & 1) * 8);
                ldsm_x4(b0, b1, b2, b3, addr);
                mma16816(sacc[2 * j],     qa[t], b0, b1);
                mma16816(sacc[2 * j + 1], qa[t], b2, b3);
            }
        }

        // ---- softmax (log2 domain, f16x2 MUFU exp) ----
        // thread rows: r1 = qb + (ln>>2), r2 = r1 + 8
        // tile i cols: 8i + (ln&3)*2 + {0,1}
        const bool tail = (l0 + 128 > L);
        #pragma unroll
        for (int i = 0; i < 16; i++) {
            #pragma unroll
            for (int q = 0; q < 4; q++) {
                float v = sacc[i][q] * sc;
                if (tail) {
                    int col = l0 + 8 * i + (ln & 3) * 2 + (q & 1);
                    if (col >= L) v = -10000.f;
                }
                sacc[i][q] = v;
            }
        }
        float mx0 = -1e30f, mx1 = -1e30f;
        #pragma unroll
        for (int i = 0; i < 16; i++) {
            mx0 = fmaxf(mx0, fmaxf(sacc[i][0], sacc[i][1]));
            mx1 = fmaxf(mx1, fmaxf(sacc[i][2], sacc[i][3]));
        }
        mx0 = fmaxf(mx0, __shfl_xor_sync(0xffffffffu, mx0, 1));
        mx0 = fmaxf(mx0, __shfl_xor_sync(0xffffffffu, mx0, 2));
        mx1 = fmaxf(mx1, __shfl_xor_sync(0xffffffffu, mx1, 1));
        mx1 = fmaxf(mx1, __shfl_xor_sync(0xffffffffu, mx1, 2));

        float mn0 = fmaxf(mrun[0], mx0), mn1 = fmaxf(mrun[1], mx1);
        float sf0 = ex2f(mrun[0] - mn0), sf1 = ex2f(mrun[1] - mn1);

        uint32_t p2[16][2];
        float rs0 = 0.f, rs1 = 0.f;
        #pragma unroll
        for (int i = 0; i < 16; i++) {
            float2 e0, e1;
            p2[i][0] = ex2_h2raw(sacc[i][0] - mn0, sacc[i][1] - mn0, &e0);
            p2[i][1] = ex2_h2raw(sacc[i][2] - mn1, sacc[i][3] - mn1, &e1);
            rs0 += e0.x + e0.y;
            rs1 += e1.x + e1.y;
        }
        rs0 += __shfl_xor_sync(0xffffffffu, rs0, 1);
        rs0 += __shfl_xor_sync(0xffffffffu, rs0, 2);
        rs1 += __shfl_xor_sync(0xffffffffu, rs1, 1);
        rs1 += __shfl_xor_sync(0xffffffffu, rs1, 2);

        mrun[0] = mn0; mrun[1] = mn1;
        lrun[0] = lrun[0] * sf0 + rs0;
        lrun[1] = lrun[1] * sf1 + rs1;

        #pragma unroll
        for (int i = 0; i < 8; i++) {
            oacc[i][0] *= sf0; oacc[i][1] *= sf0;
            oacc[i][2] *= sf1; oacc[i][3] *= sf1;
        }

        // ---- O += P @ V : P in regs (C->A layout reuse), V via ldmatrix.trans ----
        #pragma unroll
        for (int t = 0; t < 8; t++) {          // k16 over keys
            uint32_t pa[4] = {p2[2 * t][0], p2[2 * t][1], p2[2 * t + 1][0], p2[2 * t + 1][1]};
            #pragma unroll
            for (int j = 0; j < 4; j++) {      // n16 over d
                uint32_t b0, b1, b2, b3;
                uint32_t addr = vb_s + sw_off(
                    t * 16 + ((ln >> 3) & 1) * 8 + (ln & 7),
                    j * 16 + (ln >> 4) * 8);
                ldsm_x4_t(b0, b1, b2, b3, addr);
                mma16816(oacc[2 * j],     pa, b0, b1);
                mma16816(oacc[2 * j + 1], pa, b2, b3);
            }
        }
    }

    // ---- epilogue: O / l -> g_ctx ----
    float inv0 = 1.f / lrun[0], inv1 = 1.f / lrun[1];
    int r1 = t0 + qb + (ln >> 2), r2 = r1 + 8;
    size_t base1 = (size_t)(b * T + r1) * HDIM + h * DK;
    size_t base2 = (size_t)(b * T + r2) * HDIM + h * DK;
    #pragma unroll
    for (int i = 0; i < 8; i++) {
        int d = 8 * i + (ln & 3) * 2;
        *(float2*)&g_ctx[base1 + d] = make_float2(oacc[i][0] * inv0, oacc[i][1] * inv0);
        *(float2*)&g_ctx[base2 + d] = make_float2(oacc[i][2] * inv1, oacc[i][3] * inv1);
    }
}

extern "C" void kernel_launch(void* const* d_in, const int* in_sizes, int n_in,
                              void* d_out, int out_size)
{
    const float* go   = (const float*)d_in[0];
    const float* node = (const float*)d_in[1];
    const float* Wq   = (const float*)d_in[2];
    const float* Wk   = (const float*)d_in[3];
    const float* Wv   = (const float*)d_in[4];
    const float* Wp   = (const float*)d_in[5];
    const int*   lens = (const int*)d_in[6];
    float* out = (float*)d_out;

    const int T = in_sizes[0] / HDIM;   // 1024
    const int N = in_sizes[1] / HDIM;   // 24576
    const int B = in_sizes[6];          // 16

    __half *pQh, *pKh, *pVh;
    float *pC;
    cudaGetSymbolAddress((void**)&pQh, g_Qh);
    cudaGetSymbolAddress((void**)&pKh, g_Kh);
    cudaGetSymbolAddress((void**)&pVh, g_Vh);
    cudaGetSymbolAddress((void**)&pC,  g_ctx);

    setup_kernel<<<1, 32>>>(lens, B, N);

    dim3 blk(256);
    gemm128<true><<<dim3(T / 128, 2), blk>>>(go,   Wq, nullptr, pQh);
    gemm128<true><<<dim3(N / 128, 2), blk>>>(node, Wk, nullptr, pKh);
    gemm128<true><<<dim3(N / 128, 2), blk>>>(node, Wv, nullptr, pVh);

    attn_mma<<<dim3(T / 128, NHEADS, B), blk>>>(T);

    gemm128<false><<<dim3((B * T) / 128, 2), blk>>>(pC, Wp, out, nullptr);
}

// round 12
// speedup vs baseline: 5.7640x; 1.4488x over previous
#include <cuda_runtime.h>
#include <cuda_fp16.h>
#include <cstdint>

#define HDIM   256
#define DK     64
#define NHEADS 4
#define TQ     1024
#define NMAX   24576
#define BTMAX  16384
#define BMAX   64

// ---- scratch (device globals: allocation-free) ----
__device__ __half g_go16[TQ * HDIM];
__device__ __half g_nh16[NMAX * HDIM];
__device__ __half g_Wq16[HDIM * HDIM];
__device__ __half g_Wk16[HDIM * HDIM];
__device__ __half g_Wv16[HDIM * HDIM];
__device__ __half g_Qh[TQ * HDIM];
__device__ __half g_Kh[NMAX * HDIM];
__device__ __half g_Vh[NMAX * HDIM];
__device__ float  g_ctx[BTMAX * HDIM];
__device__ int    g_starts[BMAX];
__device__ int    g_lens[BMAX];

typedef unsigned long long u64;

// ---- packed f32x2 helpers ----
__device__ __forceinline__ u64 bcast2(float v) {
    u64 r; asm("mov.b64 %0, {%1, %1};" : "=l"(r) : "f"(v)); return r;
}
__device__ __forceinline__ float2 unpack2(u64 v) {
    float2 r; asm("mov.b64 {%0, %1}, %2;" : "=f"(r.x), "=f"(r.y) : "l"(v)); return r;
}
#define FMA2(d, a, b) asm("fma.rn.f32x2 %0, %1, %2, %0;" : "+l"(d) : "l"(a), "l"(b))

__device__ __forceinline__ float ex2f(float x) {
    float r; asm("ex2.approx.ftz.f32 %0, %1;" : "=f"(r) : "f"(x)); return r;
}
// packed-half exp2: returns raw f16x2 bits AND f32 values
__device__ __forceinline__ uint32_t ex2_h2raw(float a, float b, float2* out) {
    __half2 h = __floats2half2_rn(a, b);
    uint32_t hi = *(uint32_t*)&h, ho;
    asm("ex2.approx.f16x2 %0, %1;" : "=r"(ho) : "r"(hi));
    __half2 r = *(__half2*)&ho;
    *out = __half22float2(r);
    return ho;
}

__device__ __forceinline__ uint32_t smem_u32(const void* p) {
    uint32_t a;
    asm("{ .reg .u64 t; cvta.to.shared.u64 t, %1; cvt.u32.u64 %0, t; }" : "=r"(a) : "l"(p));
    return a;
}

// ---- mma.sync + ldmatrix wrappers (sm_80+, no 'a' target needed) ----
__device__ __forceinline__ void ldsm_x4(uint32_t& r0, uint32_t& r1, uint32_t& r2, uint32_t& r3, uint32_t a) {
    asm volatile("ldmatrix.sync.aligned.m8n8.x4.shared.b16 {%0,%1,%2,%3}, [%4];"
                 : "=r"(r0), "=r"(r1), "=r"(r2), "=r"(r3) : "r"(a));
}
__device__ __forceinline__ void ldsm_x4_t(uint32_t& r0, uint32_t& r1, uint32_t& r2, uint32_t& r3, uint32_t a) {
    asm volatile("ldmatrix.sync.aligned.m8n8.x4.trans.shared.b16 {%0,%1,%2,%3}, [%4];"
                 : "=r"(r0), "=r"(r1), "=r"(r2), "=r"(r3) : "r"(a));
}
__device__ __forceinline__ void mma16816(float* c, const uint32_t* a, uint32_t b0, uint32_t b1) {
    asm volatile("mma.sync.aligned.m16n8k16.row.col.f32.f16.f16.f32 "
                 "{%0,%1,%2,%3}, {%4,%5,%6,%7}, {%8,%9}, {%0,%1,%2,%3};"
                 : "+f"(c[0]), "+f"(c[1]), "+f"(c[2]), "+f"(c[3])
                 : "r"(a[0]), "r"(a[1]), "r"(a[2]), "r"(a[3]), "r"(b0), "r"(b1));
}

// byte OFFSET within a [row][64 halves] tile (128B rows, XOR-16B swizzle)
__device__ __forceinline__ uint32_t sw_off(int row, int dhalf) {
    int c = (dhalf >> 3) ^ (row & 7);
    return (uint32_t)(row * 128 + c * 16 + (dhalf & 7) * 2);
}

// ---- setup: compute segment starts; auto-detect int32 vs int64 lengths ----
__global__ void setup_kernel(const int* __restrict__ lens_raw, int B, int N) {
    if (threadIdx.x != 0 || blockIdx.x != 0) return;
    long long s32 = 0;
    for (int b = 0; b < B; b++) s32 += lens_raw[b];
    int acc = 0;
    if (s32 == (long long)N) {
        for (int b = 0; b < B; b++) { g_starts[b] = acc; g_lens[b] = lens_raw[b]; acc += lens_raw[b]; }
    } else {
        const long long* l64 = (const long long*)lens_raw;
        for (int b = 0; b < B; b++) { int L = (int)l64[b]; g_starts[b] = acc; g_lens[b] = L; acc += L; }
    }
}

// ---- f32 -> f16 convert (vectorized, grid-stride) ----
__global__ void cvt16(const float* __restrict__ src, __half* __restrict__ dst, int n4) {
    int i = blockIdx.x * blockDim.x + threadIdx.x;
    int stride = gridDim.x * blockDim.x;
    for (; i < n4; i += stride) {
        float4 v = ((const float4*)src)[i];
        __half2 h0 = __floats2half2_rn(v.x, v.y);
        __half2 h1 = __floats2half2_rn(v.z, v.w);
        ((uint2*)dst)[i] = make_uint2(*(uint32_t*)&h0, *(uint32_t*)&h1);
    }
}

// ================= HMMA GEMM: Yh = Xh @ Wh^T (f16 in, f32 accum, f16 out) ===
// 128x128 tile, 8 warps; warp owns 16 M-rows. Reuses the validated attn S-loop
// fragment pattern exactly (Ws rows = N dim, Xs rows = M dim).
__global__ void __launch_bounds__(256, 2) hgemm128(
    const __half* __restrict__ X, const __half* __restrict__ W, __half* __restrict__ Y)
{
    __shared__ __half Xs[128 * 64];
    __shared__ __half Ws[128 * 64];

    const uint32_t xb_s = smem_u32(Xs);
    const uint32_t wb_s = smem_u32(Ws);

    const int tid = threadIdx.x, wid = tid >> 5, ln = tid & 31;
    const int m0 = blockIdx.x * 128, n0 = blockIdx.y * 128;
    const int qb = wid * 16;

    float sacc[16][4];
    #pragma unroll
    for (int i = 0; i < 16; i++)
        #pragma unroll
        for (int q = 0; q < 4; q++) sacc[i][q] = 0.f;

    #pragma unroll
    for (int kc = 0; kc < 4; kc++) {
        __syncthreads();
        {
            int row = tid >> 1, seg = tid & 1;
            const uint4* xs = (const uint4*)(X + (size_t)(m0 + row) * HDIM + kc * 64 + seg * 32);
            const uint4* ws = (const uint4*)(W + (size_t)(n0 + row) * HDIM + kc * 64 + seg * 32);
            #pragma unroll
            for (int j = 0; j < 4; j++) {
                uint4 xv = xs[j];
                uint4 wv = ws[j];
                uint32_t off = sw_off(row, seg * 32 + j * 8);
                *(uint4*)((char*)Xs + off) = xv;
                *(uint4*)((char*)Ws + off) = wv;
            }
        }
        __syncthreads();

        uint32_t qa[4][4];
        #pragma unroll
        for (int t = 0; t < 4; t++) {
            uint32_t addr = xb_s + sw_off(qb + (ln & 15), t * 16 + (ln >> 4) * 8);
            ldsm_x4(qa[t][0], qa[t][1], qa[t][2], qa[t][3], addr);
        }

        #pragma unroll
        for (int t = 0; t < 4; t++) {
            #pragma unroll
            for (int j = 0; j < 8; j++) {
                uint32_t b0, b1, b2, b3;
                uint32_t addr = wb_s + sw_off(
                    j * 16 + ((ln >> 4) & 1) * 8 + (ln & 7),
                    t * 16 + ((ln >> 3) & 1) * 8);
                ldsm_x4(b0, b1, b2, b3, addr);
                mma16816(sacc[2 * j],     qa[t], b0, b1);
                mma16816(sacc[2 * j + 1], qa[t], b2, b3);
            }
        }
    }

    // epilogue: C-frag rows r1/r2, cols 8i + (ln&3)*2 — pack pairs to half2
    int r1 = qb + (ln >> 2), r2 = r1 + 8;
    #pragma unroll
    for (int i = 0; i < 16; i++) {
        int col = n0 + 8 * i + (ln & 3) * 2;
        __half2 h0 = __floats2half2_rn(sacc[i][0], sacc[i][1]);
        __half2 h1 = __floats2half2_rn(sacc[i][2], sacc[i][3]);
        *(__half2*)&Y[(size_t)(m0 + r1) * HDIM + col] = h0;
        *(__half2*)&Y[(size_t)(m0 + r2) * HDIM + col] = h1;
    }
}

// ================= f32 GEMM (FFMA2) for the output projection ===============
__global__ void __launch_bounds__(256, 2) gemm128f(
    const float* __restrict__ X, const float* __restrict__ W, float* __restrict__ Y)
{
    __shared__ float Xs[16][132];
    __shared__ float Ws[16][132];

    const int tid = threadIdx.x;
    const int tx = tid & 15, ty = tid >> 4;
    const int m0 = blockIdx.x * 128;
    const int n0 = blockIdx.y * 128;
    const int lr = tid & 127;
    const int lc = (tid >> 7) * 8;

    const float* xp = &X[(m0 + lr) * HDIM + lc];
    const float* wp = &W[(n0 + lr) * HDIM + lc];

    u64 acc2[8][4];
    #pragma unroll
    for (int r = 0; r < 8; r++)
        #pragma unroll
        for (int p = 0; p < 4; p++) acc2[r][p] = 0ull;

    float4 x0 = *(const float4*)(xp);
    float4 x1 = *(const float4*)(xp + 4);
    float4 w0 = *(const float4*)(wp);
    float4 w1 = *(const float4*)(wp + 4);

    #pragma unroll
    for (int k0 = 0; k0 < HDIM; k0 += 16) {
        __syncthreads();
        Xs[lc + 0][lr] = x0.x; Xs[lc + 1][lr] = x0.y; Xs[lc + 2][lr] = x0.z; Xs[lc + 3][lr] = x0.w;
        Xs[lc + 4][lr] = x1.x; Xs[lc + 5][lr] = x1.y; Xs[lc + 6][lr] = x1.z; Xs[lc + 7][lr] = x1.w;
        Ws[lc + 0][lr] = w0.x; Ws[lc + 1][lr] = w0.y; Ws[lc + 2][lr] = w0.z; Ws[lc + 3][lr] = w0.w;
        Ws[lc + 4][lr] = w1.x; Ws[lc + 5][lr] = w1.y; Ws[lc + 6][lr] = w1.z; Ws[lc + 7][lr] = w1.w;
        __syncthreads();

        if (k0 + 16 < HDIM) {
            x0 = *(const float4*)(xp + k0 + 16);
            x1 = *(const float4*)(xp + k0 + 20);
            w0 = *(const float4*)(wp + k0 + 16);
            w1 = *(const float4*)(wp + k0 + 20);
        }

        #pragma unroll
        for (int kk = 0; kk < 16; kk++) {
            float4 a0 = *(const float4*)&Xs[kk][ty * 4];
            float4 a1 = *(const float4*)&Xs[kk][64 + ty * 4];
            ulonglong2 b0 = *(const ulonglong2*)&Ws[kk][tx * 4];
            ulonglong2 b1 = *(const ulonglong2*)&Ws[kk][64 + tx * 4];
            float av[8] = {a0.x, a0.y, a0.z, a0.w, a1.x, a1.y, a1.z, a1.w};
            u64 bb[4] = {b0.x, b0.y, b1.x, b1.y};
            #pragma unroll
            for (int r = 0; r < 8; r++) {
                u64 ar = bcast2(av[r]);
                #pragma unroll
                for (int p = 0; p < 4; p++) FMA2(acc2[r][p], ar, bb[p]);
            }
        }
    }

    #pragma unroll
    for (int i = 0; i < 8; i++) {
        int row = m0 + ((i < 4) ? (ty * 4 + i) : (64 + ty * 4 + i - 4));
        *(ulonglong2*)&Y[row * HDIM + n0 + tx * 4]      = make_ulonglong2(acc2[i][0], acc2[i][1]);
        *(ulonglong2*)&Y[row * HDIM + n0 + 64 + tx * 4] = make_ulonglong2(acc2[i][2], acc2[i][3]);
    }
}

// ================= HMMA flash attention over ragged segments ================
__global__ void __launch_bounds__(256) attn_mma(int T)
{
    __shared__ __half Qs[128 * 64];
    __shared__ __half Ks[128 * 64];
    __shared__ __half Vs[128 * 64];

    const uint32_t qb_s = smem_u32(Qs);
    const uint32_t kb_s = smem_u32(Ks);
    const uint32_t vb_s = smem_u32(Vs);

    const int tid = threadIdx.x, wid = tid >> 5, ln = tid & 31;
    const int t0 = blockIdx.x * 128, h = blockIdx.y, b = blockIdx.z;
    const int start = g_starts[b], L = g_lens[b];
    const int qb = wid * 16;

    {
        int row = tid >> 1, seg = tid & 1;
        const uint4* src = (const uint4*)(g_Qh + (size_t)(t0 + row) * HDIM + h * DK + seg * 32);
        #pragma unroll
        for (int j = 0; j < 4; j++) {
            uint4 v = src[j];
            *(uint4*)((char*)Qs + sw_off(row, seg * 32 + j * 8)) = v;
        }
    }
    __syncthreads();

    uint32_t qa[4][4];
    #pragma unroll
    for (int t = 0; t < 4; t++) {
        uint32_t addr = qb_s + sw_off(qb + (ln & 15), t * 16 + (ln >> 4) * 8);
        ldsm_x4(qa[t][0], qa[t][1], qa[t][2], qa[t][3], addr);
    }

    float oacc[8][4];
    #pragma unroll
    for (int i = 0; i < 8; i++)
        #pragma unroll
        for (int q = 0; q < 4; q++) oacc[i][q] = 0.f;
    float mrun[2] = {-1e30f, -1e30f};
    float lrun[2] = {0.f, 0.f};

    const float sc = 0.125f * 1.4426950408889634f;

    for (int l0 = 0; l0 < L; l0 += 128) {
        __syncthreads();
        {
            int row = tid >> 1, seg = tid & 1;
            int li = l0 + row; if (li > L - 1) li = L - 1;
            size_t node = (size_t)(start + li);
            const uint4* ksrc = (const uint4*)(g_Kh + node * HDIM + h * DK + seg * 32);
            const uint4* vsrc = (const uint4*)(g_Vh + node * HDIM + h * DK + seg * 32);
            #pragma unroll
            for (int j = 0; j < 4; j++) {
                uint4 kv = ksrc[j];
                uint4 vv = vsrc[j];
                uint32_t off = sw_off(row, seg * 32 + j * 8);
                *(uint4*)((char*)Ks + off) = kv;
                *(uint4*)((char*)Vs + off) = vv;
            }
        }
        __syncthreads();

        float sacc[16][4];
        #pragma unroll
        for (int i = 0; i < 16; i++)
            #pragma unroll
            for (int q = 0; q < 4; q++) sacc[i][q] = 0.f;

        #pragma unroll
        for (int t = 0; t < 4; t++) {
            #pragma unroll
            for (int j = 0; j < 8; j++) {
                uint32_t b0, b1, b2, b3;
                uint32_t addr = kb_s + sw_off(
                    j * 16 + ((ln >> 4) & 1) * 8 + (ln & 7),
                    t * 16 + ((ln >> 3) & 1) * 8);
                ldsm_x4(b0, b1, b2, b3, addr);
                mma16816(sacc[2 * j],     qa[t], b0, b1);
                mma16816(sacc[2 * j + 1], qa[t], b2, b3);
            }
        }

        const bool tail = (l0 + 128 > L);
        #pragma unroll
        for (int i = 0; i < 16; i++) {
            #pragma unroll
            for (int q = 0; q < 4; q++) {
                float v = sacc[i][q] * sc;
                if (tail) {
                    int col = l0 + 8 * i + (ln & 3) * 2 + (q & 1);
                    if (col >= L) v = -10000.f;
                }
                sacc[i][q] = v;
            }
        }
        float mx0 = -1e30f, mx1 = -1e30f;
        #pragma unroll
        for (int i = 0; i < 16; i++) {
            mx0 = fmaxf(mx0, fmaxf(sacc[i][0], sacc[i][1]));
            mx1 = fmaxf(mx1, fmaxf(sacc[i][2], sacc[i][3]));
        }
        mx0 = fmaxf(mx0, __shfl_xor_sync(0xffffffffu, mx0, 1));
        mx0 = fmaxf(mx0, __shfl_xor_sync(0xffffffffu, mx0, 2));
        mx1 = fmaxf(mx1, __shfl_xor_sync(0xffffffffu, mx1, 1));
        mx1 = fmaxf(mx1, __shfl_xor_sync(0xffffffffu, mx1, 2));

        float mn0 = fmaxf(mrun[0], mx0), mn1 = fmaxf(mrun[1], mx1);
        float sf0 = ex2f(mrun[0] - mn0), sf1 = ex2f(mrun[1] - mn1);

        uint32_t p2[16][2];
        float rs0 = 0.f, rs1 = 0.f;
        #pragma unroll
        for (int i = 0; i < 16; i++) {
            float2 e0, e1;
            p2[i][0] = ex2_h2raw(sacc[i][0] - mn0, sacc[i][1] - mn0, &e0);
            p2[i][1] = ex2_h2raw(sacc[i][2] - mn1, sacc[i][3] - mn1, &e1);
            rs0 += e0.x + e0.y;
            rs1 += e1.x + e1.y;
        }
        rs0 += __shfl_xor_sync(0xffffffffu, rs0, 1);
        rs0 += __shfl_xor_sync(0xffffffffu, rs0, 2);
        rs1 += __shfl_xor_sync(0xffffffffu, rs1, 1);
        rs1 += __shfl_xor_sync(0xffffffffu, rs1, 2);

        mrun[0] = mn0; mrun[1] = mn1;
        lrun[0] = lrun[0] * sf0 + rs0;
        lrun[1] = lrun[1] * sf1 + rs1;

        #pragma unroll
        for (int i = 0; i < 8; i++) {
            oacc[i][0] *= sf0; oacc[i][1] *= sf0;
            oacc[i][2] *= sf1; oacc[i][3] *= sf1;
        }

        #pragma unroll
        for (int t = 0; t < 8; t++) {
            uint32_t pa[4] = {p2[2 * t][0], p2[2 * t][1], p2[2 * t + 1][0], p2[2 * t + 1][1]};
            #pragma unroll
            for (int j = 0; j < 4; j++) {
                uint32_t b0, b1, b2, b3;
                uint32_t addr = vb_s + sw_off(
                    t * 16 + ((ln >> 3) & 1) * 8 + (ln & 7),
                    j * 16 + (ln >> 4) * 8);
                ldsm_x4_t(b0, b1, b2, b3, addr);
                mma16816(oacc[2 * j],     pa, b0, b1);
                mma16816(oacc[2 * j + 1], pa, b2, b3);
            }
        }
    }

    float inv0 = 1.f / lrun[0], inv1 = 1.f / lrun[1];
    int r1 = t0 + qb + (ln >> 2), r2 = r1 + 8;
    size_t base1 = (size_t)(b * T + r1) * HDIM + h * DK;
    size_t base2 = (size_t)(b * T + r2) * HDIM + h * DK;
    #pragma unroll
    for (int i = 0; i < 8; i++) {
        int d = 8 * i + (ln & 3) * 2;
        *(float2*)&g_ctx[base1 + d] = make_float2(oacc[i][0] * inv0, oacc[i][1] * inv0);
        *(float2*)&g_ctx[base2 + d] = make_float2(oacc[i][2] * inv1, oacc[i][3] * inv1);
    }
}

extern "C" void kernel_launch(void* const* d_in, const int* in_sizes, int n_in,
                              void* d_out, int out_size)
{
    const float* go   = (const float*)d_in[0];
    const float* node = (const float*)d_in[1];
    const float* Wq   = (const float*)d_in[2];
    const float* Wk   = (const float*)d_in[3];
    const float* Wv   = (const float*)d_in[4];
    const float* Wp   = (const float*)d_in[5];
    const int*   lens = (const int*)d_in[6];
    float* out = (float*)d_out;

    const int T = in_sizes[0] / HDIM;   // 1024
    const int N = in_sizes[1] / HDIM;   // 24576
    const int B = in_sizes[6];          // 16

    __half *pGo16, *pNh16, *pWq16, *pWk16, *pWv16, *pQh, *pKh, *pVh;
    float *pC;
    cudaGetSymbolAddress((void**)&pGo16, g_go16);
    cudaGetSymbolAddress((void**)&pNh16, g_nh16);
    cudaGetSymbolAddress((void**)&pWq16, g_Wq16);
    cudaGetSymbolAddress((void**)&pWk16, g_Wk16);
    cudaGetSymbolAddress((void**)&pWv16, g_Wv16);
    cudaGetSymbolAddress((void**)&pQh, g_Qh);
    cudaGetSymbolAddress((void**)&pKh, g_Kh);
    cudaGetSymbolAddress((void**)&pVh, g_Vh);
    cudaGetSymbolAddress((void**)&pC,  g_ctx);

    setup_kernel<<<1, 32>>>(lens, B, N);

    // f32 -> f16 conversions
    cvt16<<<256, 256>>>(node, pNh16, (N * HDIM) / 4);
    cvt16<<<64, 256>>>(go,   pGo16, (T * HDIM) / 4);
    cvt16<<<32, 256>>>(Wq,   pWq16, (HDIM * HDIM) / 4);
    cvt16<<<32, 256>>>(Wk,   pWk16, (HDIM * HDIM) / 4);
    cvt16<<<32, 256>>>(Wv,   pWv16, (HDIM * HDIM) / 4);

    dim3 blk(256);
    hgemm128<<<dim3(T / 128, 2), blk>>>(pGo16, pWq16, pQh);
    hgemm128<<<dim3(N / 128, 2), blk>>>(pNh16, pWk16, pKh);
    hgemm128<<<dim3(N / 128, 2), blk>>>(pNh16, pWv16, pVh);

    attn_mma<<<dim3(T / 128, NHEADS, B), blk>>>(T);

    gemm128f<<<dim3((B * T) / 128, 2), blk>>>(pC, Wp, out);
}

// round 13
// speedup vs baseline: 6.2774x; 1.0891x over previous
#include <cuda_runtime.h>
#include <cuda_fp16.h>
#include <cstdint>

#define HDIM   256
#define DK     64
#define NHEADS 4
#define TQ     1024
#define NMAX   24576
#define BTMAX  16384
#define BMAX   64

// ---- scratch (device globals: allocation-free) ----
__device__ __half g_go16[TQ * HDIM];
__device__ __half g_nh16[NMAX * HDIM];
__device__ __half g_Wq16[HDIM * HDIM];
__device__ __half g_Wk16[HDIM * HDIM];
__device__ __half g_Wv16[HDIM * HDIM];
__device__ __half g_Qh[TQ * HDIM];
__device__ __half g_Kh[NMAX * HDIM];
__device__ __half g_Vh[NMAX * HDIM];
__device__ float  g_ctx[BTMAX * HDIM];
__device__ int    g_starts[BMAX];
__device__ int    g_lens[BMAX];

typedef unsigned long long u64;

// ---- packed f32x2 helpers ----
__device__ __forceinline__ u64 bcast2(float v) {
    u64 r; asm("mov.b64 %0, {%1, %1};" : "=l"(r) : "f"(v)); return r;
}
#define FMA2(d, a, b) asm("fma.rn.f32x2 %0, %1, %2, %0;" : "+l"(d) : "l"(a), "l"(b))

__device__ __forceinline__ float ex2f(float x) {
    float r; asm("ex2.approx.ftz.f32 %0, %1;" : "=f"(r) : "f"(x)); return r;
}
// packed-half exp2: returns raw f16x2 bits AND f32 values
__device__ __forceinline__ uint32_t ex2_h2raw(float a, float b, float2* out) {
    __half2 h = __floats2half2_rn(a, b);
    uint32_t hi = *(uint32_t*)&h, ho;
    asm("ex2.approx.f16x2 %0, %1;" : "=r"(ho) : "r"(hi));
    __half2 r = *(__half2*)&ho;
    *out = __half22float2(r);
    return ho;
}

__device__ __forceinline__ uint32_t smem_u32(const void* p) {
    uint32_t a;
    asm("{ .reg .u64 t; cvta.to.shared.u64 t, %1; cvt.u32.u64 %0, t; }" : "=r"(a) : "l"(p));
    return a;
}

// ---- cp.async (sm_80+) ----
__device__ __forceinline__ void cp_async16(uint32_t dst, const void* src) {
    asm volatile("cp.async.cg.shared.global [%0], [%1], 16;" :: "r"(dst), "l"(src));
}
#define CP_COMMIT() asm volatile("cp.async.commit_group;" ::: "memory")
#define CP_WAIT1()  asm volatile("cp.async.wait_group 1;" ::: "memory")

// ---- mma.sync + ldmatrix wrappers (sm_80+, no 'a' target needed) ----
__device__ __forceinline__ void ldsm_x4(uint32_t& r0, uint32_t& r1, uint32_t& r2, uint32_t& r3, uint32_t a) {
    asm volatile("ldmatrix.sync.aligned.m8n8.x4.shared.b16 {%0,%1,%2,%3}, [%4];"
                 : "=r"(r0), "=r"(r1), "=r"(r2), "=r"(r3) : "r"(a));
}
__device__ __forceinline__ void ldsm_x4_t(uint32_t& r0, uint32_t& r1, uint32_t& r2, uint32_t& r3, uint32_t a) {
    asm volatile("ldmatrix.sync.aligned.m8n8.x4.trans.shared.b16 {%0,%1,%2,%3}, [%4];"
                 : "=r"(r0), "=r"(r1), "=r"(r2), "=r"(r3) : "r"(a));
}
__device__ __forceinline__ void mma16816(float* c, const uint32_t* a, uint32_t b0, uint32_t b1) {
    asm volatile("mma.sync.aligned.m16n8k16.row.col.f32.f16.f16.f32 "
                 "{%0,%1,%2,%3}, {%4,%5,%6,%7}, {%8,%9}, {%0,%1,%2,%3};"
                 : "+f"(c[0]), "+f"(c[1]), "+f"(c[2]), "+f"(c[3])
                 : "r"(a[0]), "r"(a[1]), "r"(a[2]), "r"(a[3]), "r"(b0), "r"(b1));
}

// byte OFFSET within a [row][64 halves] tile (128B rows, XOR-16B swizzle)
__device__ __forceinline__ uint32_t sw_off(int row, int dhalf) {
    int c = (dhalf >> 3) ^ (row & 7);
    return (uint32_t)(row * 128 + c * 16 + (dhalf & 7) * 2);
}

// ---- setup: compute segment starts; auto-detect int32 vs int64 lengths ----
__global__ void setup_kernel(const int* __restrict__ lens_raw, int B, int N) {
    if (threadIdx.x != 0 || blockIdx.x != 0) return;
    long long s32 = 0;
    for (int b = 0; b < B; b++) s32 += lens_raw[b];
    int acc = 0;
    if (s32 == (long long)N) {
        for (int b = 0; b < B; b++) { g_starts[b] = acc; g_lens[b] = lens_raw[b]; acc += lens_raw[b]; }
    } else {
        const long long* l64 = (const long long*)lens_raw;
        for (int b = 0; b < B; b++) { int L = (int)l64[b]; g_starts[b] = acc; g_lens[b] = L; acc += L; }
    }
}

// ---- fused f32 -> f16 convert for all five tensors (one launch) ----
__global__ void cvt_all(const float* __restrict__ go, const float* __restrict__ node,
                        const float* __restrict__ Wq, const float* __restrict__ Wk,
                        const float* __restrict__ Wv,
                        __half* __restrict__ dgo, __half* __restrict__ dnode,
                        __half* __restrict__ dWq, __half* __restrict__ dWk,
                        __half* __restrict__ dWv,
                        int n_node4, int n_go4)
{
    const int NW4 = (HDIM * HDIM) / 4;
    int total = n_node4 + n_go4 + 3 * NW4;
    int i = blockIdx.x * blockDim.x + threadIdx.x;
    int stride = gridDim.x * blockDim.x;
    for (; i < total; i += stride) {
        const float* s; __half* d; int k = i;
        if (k < n_node4)                { s = node; d = dnode; }
        else if ((k -= n_node4) < n_go4){ s = go;   d = dgo;   }
        else if ((k -= n_go4) < NW4)    { s = Wq;   d = dWq;   }
        else if ((k -= NW4) < NW4)      { s = Wk;   d = dWk;   }
        else                            { k -= NW4; s = Wv; d = dWv; }
        float4 v = ((const float4*)s)[k];
        __half2 h0 = __floats2half2_rn(v.x, v.y);
        __half2 h1 = __floats2half2_rn(v.z, v.w);
        ((uint2*)d)[k] = make_uint2(*(uint32_t*)&h0, *(uint32_t*)&h1);
    }
}

// ================= HMMA GEMM: Yh = Xh @ Wh^T (f16 in, f32 accum, f16 out) ===
__global__ void __launch_bounds__(256, 2) hgemm128(
    const __half* __restrict__ X, const __half* __restrict__ W, __half* __restrict__ Y)
{
    __shared__ __half Xs[128 * 64];
    __shared__ __half Ws[128 * 64];

    const uint32_t xb_s = smem_u32(Xs);
    const uint32_t wb_s = smem_u32(Ws);

    const int tid = threadIdx.x, wid = tid >> 5, ln = tid & 31;
    const int m0 = blockIdx.x * 128, n0 = blockIdx.y * 128;
    const int qb = wid * 16;

    float sacc[16][4];
    #pragma unroll
    for (int i = 0; i < 16; i++)
        #pragma unroll
        for (int q = 0; q < 4; q++) sacc[i][q] = 0.f;

    #pragma unroll
    for (int kc = 0; kc < 4; kc++) {
        __syncthreads();
        {
            int row = tid >> 1, seg = tid & 1;
            const uint4* xs = (const uint4*)(X + (size_t)(m0 + row) * HDIM + kc * 64 + seg * 32);
            const uint4* ws = (const uint4*)(W + (size_t)(n0 + row) * HDIM + kc * 64 + seg * 32);
            #pragma unroll
            for (int j = 0; j < 4; j++) {
                uint4 xv = xs[j];
                uint4 wv = ws[j];
                uint32_t off = sw_off(row, seg * 32 + j * 8);
                *(uint4*)((char*)Xs + off) = xv;
                *(uint4*)((char*)Ws + off) = wv;
            }
        }
        __syncthreads();

        uint32_t qa[4][4];
        #pragma unroll
        for (int t = 0; t < 4; t++) {
            uint32_t addr = xb_s + sw_off(qb + (ln & 15), t * 16 + (ln >> 4) * 8);
            ldsm_x4(qa[t][0], qa[t][1], qa[t][2], qa[t][3], addr);
        }

        #pragma unroll
        for (int t = 0; t < 4; t++) {
            #pragma unroll
            for (int j = 0; j < 8; j++) {
                uint32_t b0, b1, b2, b3;
                uint32_t addr = wb_s + sw_off(
                    j * 16 + ((ln >> 4) & 1) * 8 + (ln & 7),
                    t * 16 + ((ln >> 3) & 1) * 8);
                ldsm_x4(b0, b1, b2, b3, addr);
                mma16816(sacc[2 * j],     qa[t], b0, b1);
                mma16816(sacc[2 * j + 1], qa[t], b2, b3);
            }
        }
    }

    int r1 = qb + (ln >> 2), r2 = r1 + 8;
    #pragma unroll
    for (int i = 0; i < 16; i++) {
        int col = n0 + 8 * i + (ln & 3) * 2;
        __half2 h0 = __floats2half2_rn(sacc[i][0], sacc[i][1]);
        __half2 h1 = __floats2half2_rn(sacc[i][2], sacc[i][3]);
        *(__half2*)&Y[(size_t)(m0 + r1) * HDIM + col] = h0;
        *(__half2*)&Y[(size_t)(m0 + r2) * HDIM + col] = h1;
    }
}

// ================= f32 GEMM (FFMA2) for the output projection ===============
__global__ void __launch_bounds__(256, 2) gemm128f(
    const float* __restrict__ X, const float* __restrict__ W, float* __restrict__ Y)
{
    __shared__ float Xs[16][132];
    __shared__ float Ws[16][132];

    const int tid = threadIdx.x;
    const int tx = tid & 15, ty = tid >> 4;
    const int m0 = blockIdx.x * 128;
    const int n0 = blockIdx.y * 128;
    const int lr = tid & 127;
    const int lc = (tid >> 7) * 8;

    const float* xp = &X[(m0 + lr) * HDIM + lc];
    const float* wp = &W[(n0 + lr) * HDIM + lc];

    u64 acc2[8][4];
    #pragma unroll
    for (int r = 0; r < 8; r++)
        #pragma unroll
        for (int p = 0; p < 4; p++) acc2[r][p] = 0ull;

    float4 x0 = *(const float4*)(xp);
    float4 x1 = *(const float4*)(xp + 4);
    float4 w0 = *(const float4*)(wp);
    float4 w1 = *(const float4*)(wp + 4);

    #pragma unroll
    for (int k0 = 0; k0 < HDIM; k0 += 16) {
        __syncthreads();
        Xs[lc + 0][lr] = x0.x; Xs[lc + 1][lr] = x0.y; Xs[lc + 2][lr] = x0.z; Xs[lc + 3][lr] = x0.w;
        Xs[lc + 4][lr] = x1.x; Xs[lc + 5][lr] = x1.y; Xs[lc + 6][lr] = x1.z; Xs[lc + 7][lr] = x1.w;
        Ws[lc + 0][lr] = w0.x; Ws[lc + 1][lr] = w0.y; Ws[lc + 2][lr] = w0.z; Ws[lc + 3][lr] = w0.w;
        Ws[lc + 4][lr] = w1.x; Ws[lc + 5][lr] = w1.y; Ws[lc + 6][lr] = w1.z; Ws[lc + 7][lr] = w1.w;
        __syncthreads();

        if (k0 + 16 < HDIM) {
            x0 = *(const float4*)(xp + k0 + 16);
            x1 = *(const float4*)(xp + k0 + 20);
            w0 = *(const float4*)(wp + k0 + 16);
            w1 = *(const float4*)(wp + k0 + 20);
        }

        #pragma unroll
        for (int kk = 0; kk < 16; kk++) {
            float4 a0 = *(const float4*)&Xs[kk][ty * 4];
            float4 a1 = *(const float4*)&Xs[kk][64 + ty * 4];
            ulonglong2 b0 = *(const ulonglong2*)&Ws[kk][tx * 4];
            ulonglong2 b1 = *(const ulonglong2*)&Ws[kk][64 + tx * 4];
            float av[8] = {a0.x, a0.y, a0.z, a0.w, a1.x, a1.y, a1.z, a1.w};
            u64 bb[4] = {b0.x, b0.y, b1.x, b1.y};
            #pragma unroll
            for (int r = 0; r < 8; r++) {
                u64 ar = bcast2(av[r]);
                #pragma unroll
                for (int p = 0; p < 4; p++) FMA2(acc2[r][p], ar, bb[p]);
            }
        }
    }

    #pragma unroll
    for (int i = 0; i < 8; i++) {
        int row = m0 + ((i < 4) ? (ty * 4 + i) : (64 + ty * 4 + i - 4));
        *(ulonglong2*)&Y[row * HDIM + n0 + tx * 4]      = make_ulonglong2(acc2[i][0], acc2[i][1]);
        *(ulonglong2*)&Y[row * HDIM + n0 + 64 + tx * 4] = make_ulonglong2(acc2[i][2], acc2[i][3]);
    }
}

// ================= HMMA flash attention, cp.async double-buffered ===========
// dynamic smem: Q (16KB) | K0 V0 (32KB) | K1 V1 (32KB) = 80KB
__global__ void __launch_bounds__(256) attn_mma(int T)
{
    extern __shared__ __half smh[];
    const uint32_t sbase = smem_u32(smh);
    const uint32_t qb_s  = sbase;
    const uint32_t kbs[2] = { sbase + 16384u, sbase + 49152u };
    const uint32_t vbs[2] = { sbase + 32768u, sbase + 65536u };

    const int tid = threadIdx.x, wid = tid >> 5, ln = tid & 31;
    const int t0 = blockIdx.x * 128, h = blockIdx.y, b = blockIdx.z;
    const int start = g_starts[b], L = g_lens[b];
    const int qb = wid * 16;
    const int srow = tid >> 1, sseg = tid & 1;

    // stage Q tile (plain stores)
    {
        const uint4* src = (const uint4*)(g_Qh + (size_t)(t0 + srow) * HDIM + h * DK + sseg * 32);
        #pragma unroll
        for (int j = 0; j < 4; j++) {
            uint4 v = src[j];
            *(uint4*)((char*)smh + sw_off(srow, sseg * 32 + j * 8)) = v;
        }
    }

    // prologue: issue cp.async for chunks 0 and 1
    {
        int li = srow; if (li > L - 1) li = L - 1;
        size_t node = (size_t)(start + li);
        const char* kp = (const char*)(g_Kh + node * HDIM + h * DK + sseg * 32);
        const char* vp = (const char*)(g_Vh + node * HDIM + h * DK + sseg * 32);
        #pragma unroll
        for (int j = 0; j < 4; j++) {
            uint32_t off = sw_off(srow, sseg * 32 + j * 8);
            cp_async16(kbs[0] + off, kp + j * 16);
            cp_async16(vbs[0] + off, vp + j * 16);
        }
    }
    CP_COMMIT();
    if (128 < L) {
        int li = 128 + srow; if (li > L - 1) li = L - 1;
        size_t node = (size_t)(start + li);
        const char* kp = (const char*)(g_Kh + node * HDIM + h * DK + sseg * 32);
        const char* vp = (const char*)(g_Vh + node * HDIM + h * DK + sseg * 32);
        #pragma unroll
        for (int j = 0; j < 4; j++) {
            uint32_t off = sw_off(srow, sseg * 32 + j * 8);
            cp_async16(kbs[1] + off, kp + j * 16);
            cp_async16(vbs[1] + off, vp + j * 16);
        }
    }
    CP_COMMIT();
    __syncthreads();   // Q staged (and barrier before first wait/compute)

    // Q A-fragments: constant across all chunks — load once
    uint32_t qa[4][4];
    #pragma unroll
    for (int t = 0; t < 4; t++) {
        uint32_t addr = qb_s + sw_off(qb + (ln & 15), t * 16 + (ln >> 4) * 8);
        ldsm_x4(qa[t][0], qa[t][1], qa[t][2], qa[t][3], addr);
    }

    float oacc[8][4];
    #pragma unroll
    for (int i = 0; i < 8; i++)
        #pragma unroll
        for (int q = 0; q < 4; q++) oacc[i][q] = 0.f;
    float mrun[2] = {-1e30f, -1e30f};
    float lrun[2] = {0.f, 0.f};

    const float sc = 0.125f * 1.4426950408889634f;
    int cur = 0;

    for (int l0 = 0; l0 < L; l0 += 128) {
        CP_WAIT1();        // chunk at buf[cur] complete (newest group may be pending)
        __syncthreads();   // all threads' cp.async for buf[cur] visible block-wide

        const uint32_t kb_s = kbs[cur], vb_s = vbs[cur];

        // ---- S = Q @ K^T ----
        float sacc[16][4];
        #pragma unroll
        for (int i = 0; i < 16; i++)
            #pragma unroll
            for (int q = 0; q < 4; q++) sacc[i][q] = 0.f;

        #pragma unroll
        for (int t = 0; t < 4; t++) {
            #pragma unroll
            for (int j = 0; j < 8; j++) {
                uint32_t b0, b1, b2, b3;
                uint32_t addr = kb_s + sw_off(
                    j * 16 + ((ln >> 4) & 1) * 8 + (ln & 7),
                    t * 16 + ((ln >> 3) & 1) * 8);
                ldsm_x4(b0, b1, b2, b3, addr);
                mma16816(sacc[2 * j],     qa[t], b0, b1);
                mma16816(sacc[2 * j + 1], qa[t], b2, b3);
            }
        }

        // ---- softmax (log2 domain, f16x2 MUFU exp) ----
        const bool tail = (l0 + 128 > L);
        #pragma unroll
        for (int i = 0; i < 16; i++) {
            #pragma unroll
            for (int q = 0; q < 4; q++) {
                float v = sacc[i][q] * sc;
                if (tail) {
                    int col = l0 + 8 * i + (ln & 3) * 2 + (q & 1);
                    if (col >= L) v = -10000.f;
                }
                sacc[i][q] = v;
            }
        }
        float mx0 = -1e30f, mx1 = -1e30f;
        #pragma unroll
        for (int i = 0; i < 16; i++) {
            mx0 = fmaxf(mx0, fmaxf(sacc[i][0], sacc[i][1]));
            mx1 = fmaxf(mx1, fmaxf(sacc[i][2], sacc[i][3]));
        }
        mx0 = fmaxf(mx0, __shfl_xor_sync(0xffffffffu, mx0, 1));
        mx0 = fmaxf(mx0, __shfl_xor_sync(0xffffffffu, mx0, 2));
        mx1 = fmaxf(mx1, __shfl_xor_sync(0xffffffffu, mx1, 1));
        mx1 = fmaxf(mx1, __shfl_xor_sync(0xffffffffu, mx1, 2));

        float mn0 = fmaxf(mrun[0], mx0), mn1 = fmaxf(mrun[1], mx1);
        float sf0 = ex2f(mrun[0] - mn0), sf1 = ex2f(mrun[1] - mn1);

        uint32_t p2[16][2];
        float rs0 = 0.f, rs1 = 0.f;
        #pragma unroll
        for (int i = 0; i < 16; i++) {
            float2 e0, e1;
            p2[i][0] = ex2_h2raw(sacc[i][0] - mn0, sacc[i][1] - mn0, &e0);
            p2[i][1] = ex2_h2raw(sacc[i][2] - mn1, sacc[i][3] - mn1, &e1);
            rs0 += e0.x + e0.y;
            rs1 += e1.x + e1.y;
        }
        rs0 += __shfl_xor_sync(0xffffffffu, rs0, 1);
        rs0 += __shfl_xor_sync(0xffffffffu, rs0, 2);
        rs1 += __shfl_xor_sync(0xffffffffu, rs1, 1);
        rs1 += __shfl_xor_sync(0xffffffffu, rs1, 2);

        mrun[0] = mn0; mrun[1] = mn1;
        lrun[0] = lrun[0] * sf0 + rs0;
        lrun[1] = lrun[1] * sf1 + rs1;

        #pragma unroll
        for (int i = 0; i < 8; i++) {
            oacc[i][0] *= sf0; oacc[i][1] *= sf0;
            oacc[i][2] *= sf1; oacc[i][3] *= sf1;
        }

        // ---- O += P @ V ----
        #pragma unroll
        for (int t = 0; t < 8; t++) {
            uint32_t pa[4] = {p2[2 * t][0], p2[2 * t][1], p2[2 * t + 1][0], p2[2 * t + 1][1]};
            #pragma unroll
            for (int j = 0; j < 4; j++) {
                uint32_t b0, b1, b2, b3;
                uint32_t addr = vb_s + sw_off(
                    t * 16 + ((ln >> 3) & 1) * 8 + (ln & 7),
                    j * 16 + (ln >> 4) * 8);
                ldsm_x4_t(b0, b1, b2, b3, addr);
                mma16816(oacc[2 * j],     pa, b0, b1);
                mma16816(oacc[2 * j + 1], pa, b2, b3);
            }
        }

        __syncthreads();   // all warps done reading buf[cur] before refill
        if (l0 + 256 < L) {
            int li = l0 + 256 + srow; if (li > L - 1) li = L - 1;
            size_t node = (size_t)(start + li);
            const char* kp = (const char*)(g_Kh + node * HDIM + h * DK + sseg * 32);
            const char* vp = (const char*)(g_Vh + node * HDIM + h * DK + sseg * 32);
            #pragma unroll
            for (int j = 0; j < 4; j++) {
                uint32_t off = sw_off(srow, sseg * 32 + j * 8);
                cp_async16(kbs[cur] + off, kp + j * 16);
                cp_async16(vbs[cur] + off, vp + j * 16);
            }
        }
        CP_COMMIT();
        cur ^= 1;
    }

    // ---- epilogue: O / l -> g_ctx ----
    float inv0 = 1.f / lrun[0], inv1 = 1.f / lrun[1];
    int r1 = t0 + qb + (ln >> 2), r2 = r1 + 8;
    size_t base1 = (size_t)(b * T + r1) * HDIM + h * DK;
    size_t base2 = (size_t)(b * T + r2) * HDIM + h * DK;
    #pragma unroll
    for (int i = 0; i < 8; i++) {
        int d = 8 * i + (ln & 3) * 2;
        *(float2*)&g_ctx[base1 + d] = make_float2(oacc[i][0] * inv0, oacc[i][1] * inv0);
        *(float2*)&g_ctx[base2 + d] = make_float2(oacc[i][2] * inv1, oacc[i][3] * inv1);
    }
}

extern "C" void kernel_launch(void* const* d_in, const int* in_sizes, int n_in,
                              void* d_out, int out_size)
{
    const float* go   = (const float*)d_in[0];
    const float* node = (const float*)d_in[1];
    const float* Wq   = (const float*)d_in[2];
    const float* Wk   = (const float*)d_in[3];
    const float* Wv   = (const float*)d_in[4];
    const float* Wp   = (const float*)d_in[5];
    const int*   lens = (const int*)d_in[6];
    float* out = (float*)d_out;

    const int T = in_sizes[0] / HDIM;   // 1024
    const int N = in_sizes[1] / HDIM;   // 24576
    const int B = in_sizes[6];          // 16

    __half *pGo16, *pNh16, *pWq16, *pWk16, *pWv16, *pQh, *pKh, *pVh;
    float *pC;
    cudaGetSymbolAddress((void**)&pGo16, g_go16);
    cudaGetSymbolAddress((void**)&pNh16, g_nh16);
    cudaGetSymbolAddress((void**)&pWq16, g_Wq16);
    cudaGetSymbolAddress((void**)&pWk16, g_Wk16);
    cudaGetSymbolAddress((void**)&pWv16, g_Wv16);
    cudaGetSymbolAddress((void**)&pQh, g_Qh);
    cudaGetSymbolAddress((void**)&pKh, g_Kh);
    cudaGetSymbolAddress((void**)&pVh, g_Vh);
    cudaGetSymbolAddress((void**)&pC,  g_ctx);

    setup_kernel<<<1, 32>>>(lens, B, N);

    cvt_all<<<296, 256>>>(go, node, Wq, Wk, Wv,
                          pGo16, pNh16, pWq16, pWk16, pWv16,
                          (N * HDIM) / 4, (T * HDIM) / 4);

    dim3 blk(256);
    hgemm128<<<dim3(T / 128, 2), blk>>>(pGo16, pWq16, pQh);
    hgemm128<<<dim3(N / 128, 2), blk>>>(pNh16, pWk16, pKh);
    hgemm128<<<dim3(N / 128, 2), blk>>>(pNh16, pWv16, pVh);

    const int attn_smem = 81920;
    cudaFuncSetAttribute(attn_mma, cudaFuncAttributeMaxDynamicSharedMemorySize, attn_smem);
    attn_mma<<<dim3(T / 128, NHEADS, B), blk, attn_smem>>>(T);

    gemm128f<<<dim3((B * T) / 128, 2), blk>>>(pC, Wp, out);
}

// round 15
// speedup vs baseline: 7.2264x; 1.1512x over previous
#include <cuda_runtime.h>
#include <cuda_fp16.h>
#include <cstdint>

#define HDIM   256
#define DK     64
#define NHEADS 4
#define TQ     1024
#define NMAX   24576
#define BTMAX  16384
#define BMAX   64

// ---- scratch (device globals: allocation-free) ----
__device__ __half g_go16[TQ * HDIM];
__device__ __half g_nh16[NMAX * HDIM];
__device__ __half g_Wq16[HDIM * HDIM];
__device__ __half g_Wk16[HDIM * HDIM];
__device__ __half g_Wv16[HDIM * HDIM];
__device__ __half g_Wph[HDIM * HDIM];
__device__ __half g_Wpl[HDIM * HDIM];
__device__ __half g_Qh[TQ * HDIM];
__device__ __half g_Kh[NMAX * HDIM];
__device__ __half g_Vh[NMAX * HDIM];
__device__ __half g_ctxh[BTMAX * HDIM];
__device__ __half g_ctxl[BTMAX * HDIM];
__device__ int    g_starts[BMAX];
__device__ int    g_lens[BMAX];

__device__ __forceinline__ float ex2f(float x) {
    float r; asm("ex2.approx.ftz.f32 %0, %1;" : "=f"(r) : "f"(x)); return r;
}
// packed-half exp2: returns raw f16x2 bits AND f32 values
__device__ __forceinline__ uint32_t ex2_h2raw(float a, float b, float2* out) {
    __half2 h = __floats2half2_rn(a, b);
    uint32_t hi = *(uint32_t*)&h, ho;
    asm("ex2.approx.f16x2 %0, %1;" : "=r"(ho) : "r"(hi));
    __half2 r = *(__half2*)&ho;
    *out = __half22float2(r);
    return ho;
}

__device__ __forceinline__ uint32_t smem_u32(const void* p) {
    uint32_t a;
    asm("{ .reg .u64 t; cvta.to.shared.u64 t, %1; cvt.u32.u64 %0, t; }" : "=r"(a) : "l"(p));
    return a;
}

// ---- cp.async (sm_80+) ----
__device__ __forceinline__ void cp_async16(uint32_t dst, const void* src) {
    asm volatile("cp.async.cg.shared.global [%0], [%1], 16;" :: "r"(dst), "l"(src));
}
#define CP_COMMIT() asm volatile("cp.async.commit_group;" ::: "memory")
#define CP_WAIT1()  asm volatile("cp.async.wait_group 1;" ::: "memory")

// ---- mma.sync + ldmatrix wrappers (sm_80+, no 'a' target needed) ----
__device__ __forceinline__ void ldsm_x4(uint32_t& r0, uint32_t& r1, uint32_t& r2, uint32_t& r3, uint32_t a) {
    asm volatile("ldmatrix.sync.aligned.m8n8.x4.shared.b16 {%0,%1,%2,%3}, [%4];"
                 : "=r"(r0), "=r"(r1), "=r"(r2), "=r"(r3) : "r"(a));
}
__device__ __forceinline__ void ldsm_x4_t(uint32_t& r0, uint32_t& r1, uint32_t& r2, uint32_t& r3, uint32_t a) {
    asm volatile("ldmatrix.sync.aligned.m8n8.x4.trans.shared.b16 {%0,%1,%2,%3}, [%4];"
                 : "=r"(r0), "=r"(r1), "=r"(r2), "=r"(r3) : "r"(a));
}
__device__ __forceinline__ void mma16816(float* c, const uint32_t* a, uint32_t b0, uint32_t b1) {
    asm volatile("mma.sync.aligned.m16n8k16.row.col.f32.f16.f16.f32 "
                 "{%0,%1,%2,%3}, {%4,%5,%6,%7}, {%8,%9}, {%0,%1,%2,%3};"
                 : "+f"(c[0]), "+f"(c[1]), "+f"(c[2]), "+f"(c[3])
                 : "r"(a[0]), "r"(a[1]), "r"(a[2]), "r"(a[3]), "r"(b0), "r"(b1));
}

// byte OFFSET within a [row][64 halves] tile (128B rows, XOR-16B swizzle)
__device__ __forceinline__ uint32_t sw_off(int row, int dhalf) {
    int c = (dhalf >> 3) ^ (row & 7);
    return (uint32_t)(row * 128 + c * 16 + (dhalf & 7) * 2);
}

// ---- setup: compute segment starts; auto-detect int32 vs int64 lengths ----
__global__ void setup_kernel(const int* __restrict__ lens_raw, int B, int N) {
    if (threadIdx.x != 0 || blockIdx.x != 0) return;
    long long s32 = 0;
    for (int b = 0; b < B; b++) s32 += lens_raw[b];
    int acc = 0;
    if (s32 == (long long)N) {
        for (int b = 0; b < B; b++) { g_starts[b] = acc; g_lens[b] = lens_raw[b]; acc += lens_raw[b]; }
    } else {
        const long long* l64 = (const long long*)lens_raw;
        for (int b = 0; b < B; b++) { int L = (int)l64[b]; g_starts[b] = acc; g_lens[b] = L; acc += L; }
    }
}

// ---- fused f32 -> f16 convert: go/node/Wq/Wk/Wv plain; Wp hi/lo split ----
__global__ void cvt_all(const float* __restrict__ go, const float* __restrict__ node,
                        const float* __restrict__ Wq, const float* __restrict__ Wk,
                        const float* __restrict__ Wv, const float* __restrict__ Wp,
                        __half* __restrict__ dgo, __half* __restrict__ dnode,
                        __half* __restrict__ dWq, __half* __restrict__ dWk,
                        __half* __restrict__ dWv,
                        __half* __restrict__ dWph, __half* __restrict__ dWpl,
                        int n_node4, int n_go4)
{
    const int NW4 = (HDIM * HDIM) / 4;
    int total = n_node4 + n_go4 + 4 * NW4;
    int i = blockIdx.x * blockDim.x + threadIdx.x;
    int stride = gridDim.x * blockDim.x;
    for (; i < total; i += stride) {
        int k = i;
        if (k >= n_node4 + n_go4 + 3 * NW4) {           // Wp: hi/lo split
            k -= n_node4 + n_go4 + 3 * NW4;
            float4 v = ((const float4*)Wp)[k];
            __half h0 = __float2half_rn(v.x), h1 = __float2half_rn(v.y);
            __half h2 = __float2half_rn(v.z), h3 = __float2half_rn(v.w);
            __half l0 = __float2half_rn(v.x - __half2float(h0));
            __half l1 = __float2half_rn(v.y - __half2float(h1));
            __half l2 = __float2half_rn(v.z - __half2float(h2));
            __half l3 = __float2half_rn(v.w - __half2float(h3));
            __half hh[4] = {h0, h1, h2, h3};
            __half ll[4] = {l0, l1, l2, l3};
            ((uint2*)dWph)[k] = *(uint2*)hh;
            ((uint2*)dWpl)[k] = *(uint2*)ll;
            continue;
        }
        const float* s; __half* d;
        if (k < n_node4)                 { s = node; d = dnode; }
        else if ((k -= n_node4) < n_go4) { s = go;   d = dgo;   }
        else if ((k -= n_go4) < NW4)     { s = Wq;   d = dWq;   }
        else if ((k -= NW4) < NW4)       { s = Wk;   d = dWk;   }
        else                             { k -= NW4; s = Wv; d = dWv; }
        float4 v = ((const float4*)s)[k];
        __half2 h0 = __floats2half2_rn(v.x, v.y);
        __half2 h1 = __floats2half2_rn(v.z, v.w);
        ((uint2*)d)[k] = make_uint2(*(uint32_t*)&h0, *(uint32_t*)&h1);
    }
}

// ================= HMMA GEMM, cp.async double-buffered =====================
// Yh = Xh @ Wh^T. dynamic smem: stage s at s*32768 (X), +16384 (W). 64KB.
__global__ void __launch_bounds__(256, 2) hgemm128(
    const __half* __restrict__ X, const __half* __restrict__ W, __half* __restrict__ Y)
{
    extern __shared__ char sm[];
    const uint32_t sb = smem_u32(sm);

    const int tid = threadIdx.x, wid = tid >> 5, ln = tid & 31;
    const int m0 = blockIdx.x * 128, n0 = blockIdx.y * 128;
    const int qb = wid * 16;
    const int srow = tid >> 1, sseg = tid & 1;

    const char* xg = (const char*)(X + (size_t)(m0 + srow) * HDIM + sseg * 32);
    const char* wg = (const char*)(W + (size_t)(n0 + srow) * HDIM + sseg * 32);

    // prologue: chunks 0 and 1
    #pragma unroll
    for (int kc = 0; kc < 2; kc++) {
        uint32_t base = sb + kc * 32768u;
        #pragma unroll
        for (int j = 0; j < 4; j++) {
            uint32_t off = sw_off(srow, sseg * 32 + j * 8);
            cp_async16(base + off,          xg + kc * 128 + j * 16);
            cp_async16(base + 16384u + off, wg + kc * 128 + j * 16);
        }
        CP_COMMIT();
    }

    float sacc[16][4];
    #pragma unroll
    for (int i = 0; i < 16; i++)
        #pragma unroll
        for (int q = 0; q < 4; q++) sacc[i][q] = 0.f;

    int cur = 0;
    #pragma unroll
    for (int kc = 0; kc < 4; kc++) {
        CP_WAIT1();
        __syncthreads();
        const uint32_t xb = sb + cur * 32768u, wb = xb + 16384u;

        uint32_t qa[4][4];
        #pragma unroll
        for (int t = 0; t < 4; t++) {
            uint32_t addr = xb + sw_off(qb + (ln & 15), t * 16 + (ln >> 4) * 8);
            ldsm_x4(qa[t][0], qa[t][1], qa[t][2], qa[t][3], addr);
        }
        #pragma unroll
        for (int t = 0; t < 4; t++) {
            #pragma unroll
            for (int j = 0; j < 8; j++) {
                uint32_t b0, b1, b2, b3;
                uint32_t addr = wb + sw_off(
                    j * 16 + ((ln >> 4) & 1) * 8 + (ln & 7),
                    t * 16 + ((ln >> 3) & 1) * 8);
                ldsm_x4(b0, b1, b2, b3, addr);
                mma16816(sacc[2 * j],     qa[t], b0, b1);
                mma16816(sacc[2 * j + 1], qa[t], b2, b3);
            }
        }
        __syncthreads();
        if (kc + 2 < 4) {
            uint32_t base = sb + cur * 32768u;
            #pragma unroll
            for (int j = 0; j < 4; j++) {
                uint32_t off = sw_off(srow, sseg * 32 + j * 8);
                cp_async16(base + off,          xg + (kc + 2) * 128 + j * 16);
                cp_async16(base + 16384u + off, wg + (kc + 2) * 128 + j * 16);
            }
        }
        CP_COMMIT();
        cur ^= 1;
    }

    int r1 = qb + (ln >> 2), r2 = r1 + 8;
    #pragma unroll
    for (int i = 0; i < 16; i++) {
        int col = n0 + 8 * i + (ln & 3) * 2;
        __half2 h0 = __floats2half2_rn(sacc[i][0], sacc[i][1]);
        __half2 h1 = __floats2half2_rn(sacc[i][2], sacc[i][3]);
        *(__half2*)&Y[(size_t)(m0 + r1) * HDIM + col] = h0;
        *(__half2*)&Y[(size_t)(m0 + r2) * HDIM + col] = h1;
    }
}

// ================= out-proj: Y(f32) = (Xh+Xl) @ (Wh+Wl)^T, 3-term split ====
// smem stage s at s*65536: Xh | Xl(+16384) | Wh(+32768) | Wl(+49152). 128KB.
__global__ void __launch_bounds__(256, 1) hgemm3(
    const __half* __restrict__ Xh, const __half* __restrict__ Xl,
    const __half* __restrict__ Wh, const __half* __restrict__ Wl,
    float* __restrict__ Y)
{
    extern __shared__ char sm[];
    const uint32_t sb = smem_u32(sm);

    const int tid = threadIdx.x, wid = tid >> 5, ln = tid & 31;
    const int m0 = blockIdx.x * 128, n0 = blockIdx.y * 128;
    const int qb = wid * 16;
    const int srow = tid >> 1, sseg = tid & 1;

    const char* xhg = (const char*)(Xh + (size_t)(m0 + srow) * HDIM + sseg * 32);
    const char* xlg = (const char*)(Xl + (size_t)(m0 + srow) * HDIM + sseg * 32);
    const char* whg = (const char*)(Wh + (size_t)(n0 + srow) * HDIM + sseg * 32);
    const char* wlg = (const char*)(Wl + (size_t)(n0 + srow) * HDIM + sseg * 32);

    #pragma unroll
    for (int kc = 0; kc < 2; kc++) {
        uint32_t base = sb + kc * 65536u;
        #pragma unroll
        for (int j = 0; j < 4; j++) {
            uint32_t off = sw_off(srow, sseg * 32 + j * 8);
            cp_async16(base + off,          xhg + kc * 128 + j * 16);
            cp_async16(base + 16384u + off, xlg + kc * 128 + j * 16);
            cp_async16(base + 32768u + off, whg + kc * 128 + j * 16);
            cp_async16(base + 49152u + off, wlg + kc * 128 + j * 16);
        }
        CP_COMMIT();
    }

    float sacc[16][4];
    #pragma unroll
    for (int i = 0; i < 16; i++)
        #pragma unroll
        for (int q = 0; q < 4; q++) sacc[i][q] = 0.f;

    int cur = 0;
    #pragma unroll
    for (int kc = 0; kc < 4; kc++) {
        CP_WAIT1();
        __syncthreads();
        const uint32_t xhb = sb + cur * 65536u;
        const uint32_t xlb = xhb + 16384u, whb = xhb + 32768u, wlb = xhb + 49152u;

        uint32_t qah[4][4], qal[4][4];
        #pragma unroll
        for (int t = 0; t < 4; t++) {
            uint32_t o = sw_off(qb + (ln & 15), t * 16 + (ln >> 4) * 8);
            ldsm_x4(qah[t][0], qah[t][1], qah[t][2], qah[t][3], xhb + o);
            ldsm_x4(qal[t][0], qal[t][1], qal[t][2], qal[t][3], xlb + o);
        }
        #pragma unroll
        for (int t = 0; t < 4; t++) {
            #pragma unroll
            for (int j = 0; j < 8; j++) {
                uint32_t o = sw_off(
                    j * 16 + ((ln >> 4) & 1) * 8 + (ln & 7),
                    t * 16 + ((ln >> 3) & 1) * 8);
                uint32_t h0, h1, h2, h3, l0, l1, l2, l3;
                ldsm_x4(h0, h1, h2, h3, whb + o);
                ldsm_x4(l0, l1, l2, l3, wlb + o);
                mma16816(sacc[2 * j],     qah[t], h0, h1);
                mma16816(sacc[2 * j],     qah[t], l0, l1);
                mma16816(sacc[2 * j],     qal[t], h0, h1);
                mma16816(sacc[2 * j + 1], qah[t], h2, h3);
                mma16816(sacc[2 * j + 1], qah[t], l2, l3);
                mma16816(sacc[2 * j + 1], qal[t], h2, h3);
            }
        }
        __syncthreads();
        if (kc + 2 < 4) {
            uint32_t base = sb + cur * 65536u;
            #pragma unroll
            for (int j = 0; j < 4; j++) {
                uint32_t off = sw_off(srow, sseg * 32 + j * 8);
                cp_async16(base + off,          xhg + (kc + 2) * 128 + j * 16);
                cp_async16(base + 16384u + off, xlg + (kc + 2) * 128 + j * 16);
                cp_async16(base + 32768u + off, whg + (kc + 2) * 128 + j * 16);
                cp_async16(base + 49152u + off, wlg + (kc + 2) * 128 + j * 16);
            }
        }
        CP_COMMIT();
        cur ^= 1;
    }

    int r1 = qb + (ln >> 2), r2 = r1 + 8;
    #pragma unroll
    for (int i = 0; i < 16; i++) {
        int col = n0 + 8 * i + (ln & 3) * 2;
        *(float2*)&Y[(size_t)(m0 + r1) * HDIM + col] = make_float2(sacc[i][0], sacc[i][1]);
        *(float2*)&Y[(size_t)(m0 + r2) * HDIM + col] = make_float2(sacc[i][2], sacc[i][3]);
    }
}

// ================= HMMA flash attention, cp.async double-buffered ===========
// dynamic smem: Q (16KB) | K0 V0 (32KB) | K1 V1 (32KB) = 80KB
__global__ void __launch_bounds__(256) attn_mma(int T)
{
    extern __shared__ __half smh[];
    const uint32_t sbase = smem_u32(smh);
    const uint32_t qb_s  = sbase;
    const uint32_t kbs[2] = { sbase + 16384u, sbase + 49152u };
    const uint32_t vbs[2] = { sbase + 32768u, sbase + 65536u };

    const int tid = threadIdx.x, wid = tid >> 5, ln = tid & 31;
    const int t0 = blockIdx.x * 128, h = blockIdx.y, b = blockIdx.z;
    const int start = g_starts[b], L = g_lens[b];
    const int qb = wid * 16;
    const int srow = tid >> 1, sseg = tid & 1;

    // stage Q tile (plain stores)
    {
        const uint4* src = (const uint4*)(g_Qh + (size_t)(t0 + srow) * HDIM + h * DK + sseg * 32);
        #pragma unroll
        for (int j = 0; j < 4; j++) {
            uint4 v = src[j];
            *(uint4*)((char*)smh + sw_off(srow, sseg * 32 + j * 8)) = v;
        }
    }

    // prologue: issue cp.async for chunks 0 and 1
    {
        int li = srow; if (li > L - 1) li = L - 1;
        size_t node = (size_t)(start + li);
        const char* kp = (const char*)(g_Kh + node * HDIM + h * DK + sseg * 32);
        const char* vp = (const char*)(g_Vh + node * HDIM + h * DK + sseg * 32);
        #pragma unroll
        for (int j = 0; j < 4; j++) {
            uint32_t off = sw_off(srow, sseg * 32 + j * 8);
            cp_async16(kbs[0] + off, kp + j * 16);
            cp_async16(vbs[0] + off, vp + j * 16);
        }
    }
    CP_COMMIT();
    if (128 < L) {
        int li = 128 + srow; if (li > L - 1) li = L - 1;
        size_t node = (size_t)(start + li);
        const char* kp = (const char*)(g_Kh + node * HDIM + h * DK + sseg * 32);
        const char* vp = (const char*)(g_Vh + node * HDIM + h * DK + sseg * 32);
        #pragma unroll
        for (int j = 0; j < 4; j++) {
            uint32_t off = sw_off(srow, sseg * 32 + j * 8);
            cp_async16(kbs[1] + off, kp + j * 16);
            cp_async16(vbs[1] + off, vp + j * 16);
        }
    }
    CP_COMMIT();
    __syncthreads();

    uint32_t qa[4][4];
    #pragma unroll
    for (int t = 0; t < 4; t++) {
        uint32_t addr = qb_s + sw_off(qb + (ln & 15), t * 16 + (ln >> 4) * 8);
        ldsm_x4(qa[t][0], qa[t][1], qa[t][2], qa[t][3], addr);
    }

    float oacc[8][4];
    #pragma unroll
    for (int i = 0; i < 8; i++)
        #pragma unroll
        for (int q = 0; q < 4; q++) oacc[i][q] = 0.f;
    float mrun[2] = {-1e30f, -1e30f};
    float lrun[2] = {0.f, 0.f};

    const float sc = 0.125f * 1.4426950408889634f;
    int cur = 0;

    for (int l0 = 0; l0 < L; l0 += 128) {
        CP_WAIT1();
        __syncthreads();

        const uint32_t kb_s = kbs[cur], vb_s = vbs[cur];

        float sacc[16][4];
        #pragma unroll
        for (int i = 0; i < 16; i++)
            #pragma unroll
            for (int q = 0; q < 4; q++) sacc[i][q] = 0.f;

        #pragma unroll
        for (int t = 0; t < 4; t++) {
            #pragma unroll
            for (int j = 0; j < 8; j++) {
                uint32_t b0, b1, b2, b3;
                uint32_t addr = kb_s + sw_off(
                    j * 16 + ((ln >> 4) & 1) * 8 + (ln & 7),
                    t * 16 + ((ln >> 3) & 1) * 8);
                ldsm_x4(b0, b1, b2, b3, addr);
                mma16816(sacc[2 * j],     qa[t], b0, b1);
                mma16816(sacc[2 * j + 1], qa[t], b2, b3);
            }
        }

        const bool tail = (l0 + 128 > L);
        #pragma unroll
        for (int i = 0; i < 16; i++) {
            #pragma unroll
            for (int q = 0; q < 4; q++) {
                float v = sacc[i][q] * sc;
                if (tail) {
                    int col = l0 + 8 * i + (ln & 3) * 2 + (q & 1);
                    if (col >= L) v = -10000.f;
                }
                sacc[i][q] = v;
            }
        }
        float mx0 = -1e30f, mx1 = -1e30f;
        #pragma unroll
        for (int i = 0; i < 16; i++) {
            mx0 = fmaxf(mx0, fmaxf(sacc[i][0], sacc[i][1]));
            mx1 = fmaxf(mx1, fmaxf(sacc[i][2], sacc[i][3]));
        }
        mx0 = fmaxf(mx0, __shfl_xor_sync(0xffffffffu, mx0, 1));
        mx0 = fmaxf(mx0, __shfl_xor_sync(0xffffffffu, mx0, 2));
        mx1 = fmaxf(mx1, __shfl_xor_sync(0xffffffffu, mx1, 1));
        mx1 = fmaxf(mx1, __shfl_xor_sync(0xffffffffu, mx1, 2));

        float mn0 = fmaxf(mrun[0], mx0), mn1 = fmaxf(mrun[1], mx1);
        float sf0 = ex2f(mrun[0] - mn0), sf1 = ex2f(mrun[1] - mn1);

        uint32_t p2[16][2];
        float rs0 = 0.f, rs1 = 0.f;
        #pragma unroll
        for (int i = 0; i < 16; i++) {
            float2 e0, e1;
            p2[i][0] = ex2_h2raw(sacc[i][0] - mn0, sacc[i][1] - mn0, &e0);
            p2[i][1] = ex2_h2raw(sacc[i][2] - mn1, sacc[i][3] - mn1, &e1);
            rs0 += e0.x + e0.y;
            rs1 += e1.x + e1.y;
        }
        rs0 += __shfl_xor_sync(0xffffffffu, rs0, 1);
        rs0 += __shfl_xor_sync(0xffffffffu, rs0, 2);
        rs1 += __shfl_xor_sync(0xffffffffu, rs1, 1);
        rs1 += __shfl_xor_sync(0xffffffffu, rs1, 2);

        mrun[0] = mn0; mrun[1] = mn1;
        lrun[0] = lrun[0] * sf0 + rs0;
        lrun[1] = lrun[1] * sf1 + rs1;

        #pragma unroll
        for (int i = 0; i < 8; i++) {
            oacc[i][0] *= sf0; oacc[i][1] *= sf0;
            oacc[i][2] *= sf1; oacc[i][3] *= sf1;
        }

        #pragma unroll
        for (int t = 0; t < 8; t++) {
            uint32_t pa[4] = {p2[2 * t][0], p2[2 * t][1], p2[2 * t + 1][0], p2[2 * t + 1][1]};
            #pragma unroll
            for (int j = 0; j < 4; j++) {
                uint32_t b0, b1, b2, b3;
                uint32_t addr = vb_s + sw_off(
                    t * 16 + ((ln >> 3) & 1) * 8 + (ln & 7),
                    j * 16 + (ln >> 4) * 8);
                ldsm_x4_t(b0, b1, b2, b3, addr);
                mma16816(oacc[2 * j],     pa, b0, b1);
                mma16816(oacc[2 * j + 1], pa, b2, b3);
            }
        }

        __syncthreads();
        if (l0 + 256 < L) {
            int li = l0 + 256 + srow; if (li > L - 1) li = L - 1;
            size_t node = (size_t)(start + li);
            const char* kp = (const char*)(g_Kh + node * HDIM + h * DK + sseg * 32);
            const char* vp = (const char*)(g_Vh + node * HDIM + h * DK + sseg * 32);
            #pragma unroll
            for (int j = 0; j < 4; j++) {
                uint32_t off = sw_off(srow, sseg * 32 + j * 8);
                cp_async16(kbs[cur] + off, kp + j * 16);
                cp_async16(vbs[cur] + off, vp + j * 16);
            }
        }
        CP_COMMIT();
        cur ^= 1;
    }

    // ---- epilogue: O / l -> ctx hi/lo f16 split ----
    float inv0 = 1.f / lrun[0], inv1 = 1.f / lrun[1];
    int r1 = t0 + qb + (ln >> 2), r2 = r1 + 8;
    size_t base1 = (size_t)(b * T + r1) * HDIM + h * DK;
    size_t base2 = (size_t)(b * T + r2) * HDIM + h * DK;
    #pragma unroll
    for (int i = 0; i < 8; i++) {
        int d = 8 * i + (ln & 3) * 2;
        float v0 = oacc[i][0] * inv0, v1 = oacc[i][1] * inv0;
        float v2 = oacc[i][2] * inv1, v3 = oacc[i][3] * inv1;
        __half h0 = __float2half_rn(v0), h1 = __float2half_rn(v1);
        __half h2 = __float2half_rn(v2), h3 = __float2half_rn(v3);
        __half2 hp1 = __halves2half2(h0, h1);
        __half2 hp2 = __halves2half2(h2, h3);
        __half2 lp1 = __floats2half2_rn(v0 - __half2float(h0), v1 - __half2float(h1));
        __half2 lp2 = __floats2half2_rn(v2 - __half2float(h2), v3 - __half2float(h3));
        *(__half2*)&g_ctxh[base1 + d] = hp1;
        *(__half2*)&g_ctxl[base1 + d] = lp1;
        *(__half2*)&g_ctxh[base2 + d] = hp2;
        *(__half2*)&g_ctxl[base2 + d] = lp2;
    }
}

extern "C" void kernel_launch(void* const* d_in, const int* in_sizes, int n_in,
                              void* d_out, int out_size)
{
    const float* go   = (const float*)d_in[0];
    const float* node = (const float*)d_in[1];
    const float* Wq   = (const float*)d_in[2];
    const float* Wk   = (const float*)d_in[3];
    const float* Wv   = (const float*)d_in[4];
    const float* Wp   = (const float*)d_in[5];
    const int*   lens = (const int*)d_in[6];
    float* out = (float*)d_out;

    const int T = in_sizes[0] / HDIM;   // 1024
    const int N = in_sizes[1] / HDIM;   // 24576
    const int B = in_sizes[6];          // 16

    __half *pGo16, *pNh16, *pWq16, *pWk16, *pWv16, *pWph, *pWpl;
    __half *pQh, *pKh, *pVh, *pCh, *pCl;
    cudaGetSymbolAddress((void**)&pGo16, g_go16);
    cudaGetSymbolAddress((void**)&pNh16, g_nh16);
    cudaGetSymbolAddress((void**)&pWq16, g_Wq16);
    cudaGetSymbolAddress((void**)&pWk16, g_Wk16);
    cudaGetSymbolAddress((void**)&pWv16, g_Wv16);
    cudaGetSymbolAddress((void**)&pWph, g_Wph);
    cudaGetSymbolAddress((void**)&pWpl, g_Wpl);
    cudaGetSymbolAddress((void**)&pQh, g_Qh);
    cudaGetSymbolAddress((void**)&pKh, g_Kh);
    cudaGetSymbolAddress((void**)&pVh, g_Vh);
    cudaGetSymbolAddress((void**)&pCh, g_ctxh);
    cudaGetSymbolAddress((void**)&pCl, g_ctxl);

    setup_kernel<<<1, 32>>>(lens, B, N);

    cvt_all<<<296, 256>>>(go, node, Wq, Wk, Wv, Wp,
                          pGo16, pNh16, pWq16, pWk16, pWv16, pWph, pWpl,
                          (N * HDIM) / 4, (T * HDIM) / 4);

    dim3 blk(256);
    const int hg_smem = 65536;
    cudaFuncSetAttribute(hgemm128, cudaFuncAttributeMaxDynamicSharedMemorySize, hg_smem);
    hgemm128<<<dim3(T / 128, 2), blk, hg_smem>>>(pGo16, pWq16, pQh);
    hgemm128<<<dim3(N / 128, 2), blk, hg_smem>>>(pNh16, pWk16, pKh);
    hgemm128<<<dim3(N / 128, 2), blk, hg_smem>>>(pNh16, pWv16, pVh);

    const int attn_smem = 81920;
    cudaFuncSetAttribute(attn_mma, cudaFuncAttributeMaxDynamicSharedMemorySize, attn_smem);
    attn_mma<<<dim3(T / 128, NHEADS, B), blk, attn_smem>>>(T);

    const int hg3_smem = 131072;
    cudaFuncSetAttribute(hgemm3, cudaFuncAttributeMaxDynamicSharedMemorySize, hg3_smem);
    hgemm3<<<dim3((B * T) / 128, 2), blk, hg3_smem>>>(pCh, pCl, pWph, pWpl, out);
}